// round 13
// baseline (speedup 1.0000x reference)
#include <cuda_runtime.h>
#include <math.h>
#include <stdint.h>

#define BB 8
#define SS 2048
#define HH 1024
#define CC 64
#define NCH 32
#define NN 512      /* BB*CC rows per chunk */
#define II 2048     /* INTER */
#define NROWS 16384 /* BB*SS */
#define NBLK 256    /* persistent scan blocks (2/SM on >=128 SMs: always resident) */

#define EPI_NONE 0
#define EPI_SILU 1
#define EPI_SILU_AUX 2
#define EPI_DSILU 3
#define EPI_GRAD 4
#define EPI_GRAD_LN 5

// ---------------- device scratch (no allocation allowed) ----------------
__device__ __align__(16) float g_k[NROWS * HH];
__device__ __align__(16) float g_v[NROWS * HH];
__device__ __align__(16) float g_q[NROWS * HH];
__device__ __align__(16) float g_kall[NROWS * HH];
__device__ __align__(16) float g_vall[NROWS * HH];
__device__ __align__(16) float g_w0[II * HH];
__device__ __align__(16) float g_w1[HH * II];
__device__ __align__(16) float g_ln[HH];
__device__ __align__(16) float g_s0[II * HH];
__device__ __align__(16) float g_s1[HH * II];
__device__ __align__(16) float g_sln[HH];
__device__ __align__(16) float g_z[NN * II];
__device__ __align__(16) float g_h[NN * II];
__device__ __align__(16) float g_dz[NN * II];
__device__ __align__(16) float g_y[4 * NN * HH];    /* y split-K partials */
__device__ __align__(16) float g_dy[NN * HH];
__device__ __align__(16) float g_dw0[II * HH];
__device__ __align__(16) float g_dw1[HH * II];
__device__ __align__(16) float g_dlnA[NCH * HH];
__device__ __align__(16) float g_gnormA[NCH];
__device__ __align__(16) float g_h2[NROWS * II];
__device__ __align__(16) float g_y2[NROWS * HH];
__device__ __align__(16) float g_dotA[BB * NCH];
__device__ __align__(16) float g_dotT[BB * NCH];
__device__ __align__(16) float g_dotE[BB * NCH];
__device__ __align__(16) float g_beta[NCH];
__device__ __align__(16) float g_eta[NCH];
__device__ __align__(16) float g_theta[BB * NCH];
__device__ unsigned g_bar_cnt;
__device__ unsigned g_bar_gen;

// ---------------- helpers ----------------
__device__ __forceinline__ float sigm(float x) { return 1.f / (1.f + expf(-x)); }
__device__ __forceinline__ float silu_f(float x) { return x / (1.f + expf(-x)); }
__device__ __forceinline__ float dsilu_f(float x) {
    float s = 1.f / (1.f + expf(-x));
    return s * (1.f + x * (1.f - s));
}

__device__ __forceinline__ void mma8(float* d, const uint32_t* a, const uint32_t* b) {
    asm volatile(
        "mma.sync.aligned.m16n8k8.row.col.f32.tf32.tf32.f32 "
        "{%0,%1,%2,%3}, {%4,%5,%6,%7}, {%8,%9}, {%0,%1,%2,%3};"
        : "+f"(d[0]), "+f"(d[1]), "+f"(d[2]), "+f"(d[3])
        : "r"(a[0]), "r"(a[1]), "r"(a[2]), "r"(a[3]), "r"(b[0]), "r"(b[1]));
}

#define LDSM_X4(r0, r1, r2, r3, addr) \
    asm volatile("ldmatrix.sync.aligned.m8n8.x4.shared.b16 {%0,%1,%2,%3}, [%4];" \
                 : "=r"(r0), "=r"(r1), "=r"(r2), "=r"(r3) : "r"(addr))

__device__ __forceinline__ void cpa16(float* dst, const float* src) {
    uint32_t d = (uint32_t)__cvta_generic_to_shared(dst);
    asm volatile("cp.async.cg.shared.global [%0], [%1], 16;\n" :: "r"(d), "l"(src));
}
__device__ __forceinline__ void cpa_commit() { asm volatile("cp.async.commit_group;\n"); }

__device__ __forceinline__ float block_sum(float v) {
    __shared__ float sh[32];
    __shared__ float tot;
    int lane = threadIdx.x & 31;
    int w = threadIdx.x >> 5;
#pragma unroll
    for (int o = 16; o > 0; o >>= 1) v += __shfl_xor_sync(0xffffffffu, v, o);
    if (lane == 0) sh[w] = v;
    __syncthreads();
    if (w == 0) {
        float r = (lane < (blockDim.x >> 5)) ? sh[lane] : 0.f;
#pragma unroll
        for (int o = 16; o > 0; o >>= 1) r += __shfl_xor_sync(0xffffffffu, r, o);
        if (lane == 0) tot = r;
    }
    __syncthreads();
    return tot;
}

// grid-wide barrier for the persistent scan kernel (all NBLK blocks resident)
__device__ __forceinline__ void grid_sync() {
    __syncthreads();
    if (threadIdx.x == 0) {
        __threadfence();
        unsigned my = atomicAdd(&g_bar_gen, 0u);
        unsigned old = atomicInc(&g_bar_cnt, NBLK - 1);
        if (old == NBLK - 1) {
            atomicAdd(&g_bar_gen, 1u);
        } else {
            int slp = 32;
            while (atomicAdd(&g_bar_gen, 0u) == my) {
                __nanosleep(slp);
                if (slp < 256) slp <<= 1;
            }
        }
    }
    __syncthreads();
}

// ---------------- tf32 tensor-core GEMM body (cp.async + LDSM fragments) ------
template<int BM, int BN, int WM, int WN, int NWARP, bool AT, bool BT>
__device__ __forceinline__ void gemm_body(
    float* sm,
    const float* __restrict__ A, const float* __restrict__ B,
    float* __restrict__ C, float* __restrict__ aux, float* __restrict__ gn,
    int M, int N, int K, int lda, int ldb, int epi, int bx, int by)
{
    constexpr int NT = NWARP * 32;
    constexpr int SA = BM + 8;
    constexpr int SB = BN + 8;
    constexpr int ASZ = AT ? BM * 36 : 32 * SA;
    constexpr int BSZ = BT ? BN * 36 : 32 * SB;
    constexpr int PA = AT ? (BM * 8) / NT : (32 * (BM / 4)) / NT;
    constexpr int PB = BT ? (BN * 8) / NT : (32 * (BN / 4)) / NT;
    constexpr int WGM = BM / WM;
    constexpr int MI = WM / 16, NI = WN / 8;

    float* Ab[2] = { sm, sm + ASZ };
    float* Bb[2] = { sm + 2 * ASZ, sm + 2 * ASZ + BSZ };

    const int t = threadIdx.x;
    const int bm = by * BM, bn = bx * BN;
    const int wid = t >> 5, lane = t & 31;
    const int wm = (wid % WGM) * WM;
    const int wn = (wid / WGM) * WN;
    const int gp = lane >> 2, kq = lane & 3;

    const int lane_row = lane & 7;
    const uint32_t ao = (uint32_t)(((wm + lane_row + ((lane >> 3) & 1) * 8) * 36 +
                                    ((lane >> 4) & 1) * 4) * 4);
    const uint32_t bo = (uint32_t)(((wn + lane_row + ((lane >> 4) & 1) * 8) * 36 +
                                    ((lane >> 3) & 1) * 4) * 4);
    uint32_t AsU[2] = { (uint32_t)__cvta_generic_to_shared(Ab[0]),
                        (uint32_t)__cvta_generic_to_shared(Ab[1]) };
    uint32_t BsU[2] = { (uint32_t)__cvta_generic_to_shared(Bb[0]),
                        (uint32_t)__cvta_generic_to_shared(Bb[1]) };

    float acc[MI][NI][4];
#pragma unroll
    for (int i = 0; i < MI; i++)
#pragma unroll
        for (int j = 0; j < NI; j++)
#pragma unroll
            for (int q = 0; q < 4; q++) acc[i][j][q] = 0.f;

    auto issue = [&](int k0, int buf) {
        float* As = Ab[buf];
        float* Bs = Bb[buf];
#pragma unroll
        for (int p = 0; p < PA; p++) {
            int idx = p * NT + t;
            if constexpr (AT) {
                int row = idx >> 3, seg = idx & 7;
                cpa16(As + row * 36 + seg * 4, A + (size_t)(bm + row) * lda + k0 + seg * 4);
            } else {
                int kk = idx / (BM / 4), mseg = idx % (BM / 4);
                cpa16(As + kk * SA + mseg * 4, A + (size_t)(k0 + kk) * lda + bm + mseg * 4);
            }
        }
#pragma unroll
        for (int p = 0; p < PB; p++) {
            int idx = p * NT + t;
            if constexpr (BT) {
                int row = idx >> 3, seg = idx & 7;
                cpa16(Bs + row * 36 + seg * 4, B + (size_t)(bn + row) * ldb + k0 + seg * 4);
            } else {
                int kk = idx / (BN / 4), nseg = idx % (BN / 4);
                cpa16(Bs + kk * SB + nseg * 4, B + (size_t)(k0 + kk) * ldb + bn + nseg * 4);
            }
        }
        cpa_commit();
    };

    issue(0, 0);
    const int nit = K / 32;
    for (int it = 0; it < nit; it++) {
        if (it + 1 < nit) {
            issue((it + 1) * 32, (it + 1) & 1);
            asm volatile("cp.async.wait_group 1;\n");
        } else {
            asm volatile("cp.async.wait_group 0;\n");
        }
        __syncthreads();
        const int buf = it & 1;
        const float* As = Ab[buf];
        const float* Bs = Bb[buf];
        const uint32_t AsB = AsU[buf], BsB = BsU[buf];
#pragma unroll
        for (int ks = 0; ks < 4; ks++) {
            const int k8 = ks * 8 + kq;
            uint32_t af[MI][4], bf[NI][2];
            if constexpr (AT) {
#pragma unroll
                for (int mi = 0; mi < MI; mi++)
                    LDSM_X4(af[mi][0], af[mi][1], af[mi][2], af[mi][3],
                            AsB + ao + mi * 2304 + ks * 32);
            } else {
#pragma unroll
                for (int mi = 0; mi < MI; mi++) {
                    int r0 = wm + mi * 16 + gp;
                    af[mi][0] = __float_as_uint(As[k8 * SA + r0]);
                    af[mi][1] = __float_as_uint(As[k8 * SA + r0 + 8]);
                    af[mi][2] = __float_as_uint(As[(k8 + 4) * SA + r0]);
                    af[mi][3] = __float_as_uint(As[(k8 + 4) * SA + r0 + 8]);
                }
            }
            if constexpr (BT) {
#pragma unroll
                for (int q = 0; q < NI / 2; q++)
                    LDSM_X4(bf[2 * q][0], bf[2 * q][1], bf[2 * q + 1][0], bf[2 * q + 1][1],
                            BsB + bo + q * 2304 + ks * 32);
            } else {
#pragma unroll
                for (int ni = 0; ni < NI; ni++) {
                    int c0 = wn + ni * 8 + gp;
                    bf[ni][0] = __float_as_uint(Bs[k8 * SB + c0]);
                    bf[ni][1] = __float_as_uint(Bs[(k8 + 4) * SB + c0]);
                }
            }
#pragma unroll
            for (int mi = 0; mi < MI; mi++)
#pragma unroll
                for (int ni = 0; ni < NI; ni++)
                    mma8(acc[mi][ni], af[mi], bf[ni]);
        }
        __syncthreads();
    }

    // epilogue
    float gs = 0.f;
#pragma unroll
    for (int mi = 0; mi < MI; mi++) {
#pragma unroll
        for (int ni = 0; ni < NI; ni++) {
            int r0 = bm + wm + mi * 16 + gp;
            int c = bn + wn + ni * 8 + kq * 2;
            size_t o0 = (size_t)r0 * N + c;
            size_t o1 = (size_t)(r0 + 8) * N + c;
            float2 v0 = make_float2(acc[mi][ni][0], acc[mi][ni][1]);
            float2 v1 = make_float2(acc[mi][ni][2], acc[mi][ni][3]);
            if (epi == EPI_SILU) {
                v0.x = silu_f(v0.x); v0.y = silu_f(v0.y);
                v1.x = silu_f(v1.x); v1.y = silu_f(v1.y);
            } else if (epi == EPI_SILU_AUX) {
                *(float2*)(aux + o0) = v0;
                *(float2*)(aux + o1) = v1;
                v0.x = silu_f(v0.x); v0.y = silu_f(v0.y);
                v1.x = silu_f(v1.x); v1.y = silu_f(v1.y);
            } else if (epi == EPI_DSILU) {
                float2 z0 = *(const float2*)(aux + o0);
                float2 z1 = *(const float2*)(aux + o1);
                v0.x *= dsilu_f(z0.x); v0.y *= dsilu_f(z0.y);
                v1.x *= dsilu_f(z1.x); v1.y *= dsilu_f(z1.y);
            } else if (epi >= EPI_GRAD) {
                gs += v0.x * v0.x + v0.y * v0.y + v1.x * v1.x + v1.y * v1.y;
            }
            *(float2*)(C + o0) = v0;
            *(float2*)(C + o1) = v1;
        }
    }
    if (epi >= EPI_GRAD) {
        gs = block_sum(gs);
        if (t == 0) atomicAdd(gn, gs);
        if (epi == EPI_GRAD_LN && bx == 0 && by == 0) {
            float s = 0.f;
            for (int i = t; i < HH; i += NT) { float d = aux[i]; s += d * d; }
            s = block_sum(s);
            if (t == 0) atomicAdd(gn, s);
        }
    }
}

template<int BM, int BN, int WM, int WN, int NWARP, bool AT, bool BT>
__global__ __launch_bounds__(NWARP * 32) void gemm_tc(
    const float* __restrict__ A, const float* __restrict__ B,
    float* __restrict__ C, float* __restrict__ aux, float* __restrict__ gn,
    int M, int N, int K, int lda, int ldb, int epi)
{
    extern __shared__ float sm[];
    gemm_body<BM, BN, WM, WN, NWARP, AT, BT>(sm, A, B, C, aux, gn, M, N, K, lda, ldb,
                                             epi, blockIdx.x, blockIdx.y);
}

// ---------------- persistent scan kernel: whole 32-chunk loop, 1 launch ------
__global__ __launch_bounds__(128) void scan_persistent() {
    extern __shared__ float sm[];
    const int bid = blockIdx.x;
    const int t = threadIdx.x;

    for (int c = 0; c < NCH; c++) {
        const float* kc = g_kall + (size_t)c * NN * HH;
        const float* vc = g_vall + (size_t)c * NN * HH;
        float* gn = g_gnormA + c;
        float* dln = g_dlnA + c * HH;

        // ---- phase 1: z = kc @ w0^T, h = silu(z)  (256 tiles of 64x64) ----
        for (int i = bid; i < (II / 64) * (NN / 64); i += NBLK)
            gemm_body<64, 64, 32, 32, 4, true, true>(
                sm, kc, g_w0, g_h, g_z, nullptr, NN, II, HH, HH, HH,
                EPI_SILU_AUX, i % (II / 64), i / (II / 64));
        grid_sync();

        // ---- phase 2: y partials split-K=4 (256 tiles of 64x128) ----
        for (int i = bid; i < (HH / 128) * (NN / 64) * 4; i += NBLK) {
            int s = i / ((HH / 128) * (NN / 64));
            int r = i % ((HH / 128) * (NN / 64));
            gemm_body<64, 128, 32, 64, 4, true, true>(
                sm, g_h + s * (II / 4), g_w1 + s * (II / 4),
                g_y + (size_t)s * NN * HH, nullptr, nullptr,
                NN, HH, II / 4, II, II, EPI_NONE, r % (HH / 128), r / (HH / 128));
        }
        grid_sync();

        // ---- phase 3: backward rmsnorm+MSE (512 rows, 128 threads/row) ----
        for (int r = bid; r < NN; r += NBLK) {
            int b = r >> 6;
            float4 yv[2];
            float ssl = 0.f;
#pragma unroll
            for (int hx = 0; hx < 2; hx++) {
                int q = t + hx * 128;
                float4 y0 = ((const float4*)(g_y + (size_t)r * HH))[q];
                float4 y1 = ((const float4*)(g_y + (size_t)(NN + r) * HH))[q];
                float4 y2 = ((const float4*)(g_y + (size_t)(2 * NN + r) * HH))[q];
                float4 y3 = ((const float4*)(g_y + (size_t)(3 * NN + r) * HH))[q];
                yv[hx].x = (y0.x + y1.x) + (y2.x + y3.x);
                yv[hx].y = (y0.y + y1.y) + (y2.y + y3.y);
                yv[hx].z = (y0.z + y1.z) + (y2.z + y3.z);
                yv[hx].w = (y0.w + y1.w) + (y2.w + y3.w);
                ssl += yv[hx].x * yv[hx].x + yv[hx].y * yv[hx].y +
                       yv[hx].z * yv[hx].z + yv[hx].w * yv[hx].w;
            }
            float ss = block_sum(ssl);
            float rs = rsqrtf(ss / HH + 1e-6f);
            float th = g_theta[b * NCH + c];
            float scale = 2.f * th / ((float)NN * (float)HH);
            float4 ggv[2], l4v[2];
            float svl = 0.f;
#pragma unroll
            for (int hx = 0; hx < 2; hx++) {
                int q = t + hx * 128;
                float4 k4 = ((const float4*)(kc + (size_t)r * HH))[q];
                float4 v4 = ((const float4*)(vc + (size_t)r * HH))[q];
                float4 l4 = ((const float4*)g_ln)[q];
                l4v[hx] = l4;
                float4 gg;
                gg.x = scale * (k4.x + yv[hx].x * rs * l4.x - v4.x);
                gg.y = scale * (k4.y + yv[hx].y * rs * l4.y - v4.y);
                gg.z = scale * (k4.z + yv[hx].z * rs * l4.z - v4.z);
                gg.w = scale * (k4.w + yv[hx].w * rs * l4.w - v4.w);
                ggv[hx] = gg;
                svl += gg.x * l4.x * yv[hx].x + gg.y * l4.y * yv[hx].y +
                       gg.z * l4.z * yv[hx].z + gg.w * l4.w * yv[hx].w;
            }
            float sv = block_sum(svl);
            float c3 = rs * rs * rs * sv / (float)HH;
#pragma unroll
            for (int hx = 0; hx < 2; hx++) {
                int q = t + hx * 128;
                float4 gg = ggv[hx], l4 = l4v[hx];
                float4 dy;
                dy.x = rs * gg.x * l4.x - c3 * yv[hx].x;
                dy.y = rs * gg.y * l4.y - c3 * yv[hx].y;
                dy.z = rs * gg.z * l4.z - c3 * yv[hx].z;
                dy.w = rs * gg.w * l4.w - c3 * yv[hx].w;
                ((float4*)(g_dy + (size_t)r * HH))[q] = dy;
                atomicAdd(&dln[q * 4 + 0], gg.x * yv[hx].x * rs);
                atomicAdd(&dln[q * 4 + 1], gg.y * yv[hx].y * rs);
                atomicAdd(&dln[q * 4 + 2], gg.z * yv[hx].z * rs);
                atomicAdd(&dln[q * 4 + 3], gg.w * yv[hx].w * rs);
            }
        }
        grid_sync();

        // ---- phase 4: dz (256 tiles) + dw1 (512 tiles) ----
        for (int i = bid; i < 768; i += NBLK) {
            if (i < 256)
                gemm_body<64, 64, 32, 32, 4, true, false>(
                    sm, g_dy, g_w1, g_dz, g_z, nullptr, NN, II, HH, HH, II,
                    EPI_DSILU, i % 32, i / 32);
            else {
                int j = i - 256;
                gemm_body<64, 64, 32, 32, 4, false, false>(
                    sm, g_dy, g_h, g_dw1, nullptr, gn, HH, II, NN, HH, II,
                    EPI_GRAD, j % 32, j / 32);
            }
        }
        grid_sync();

        // ---- phase 5: dw0 = dz^T @ kc (512 tiles) + dln^2 ----
        for (int i = bid; i < (HH / 64) * (II / 64); i += NBLK)
            gemm_body<64, 64, 32, 32, 4, false, false>(
                sm, g_dz, kc, g_dw0, dln, gn, II, HH, NN, II, HH,
                EPI_GRAD_LN, i % (HH / 64), i / (HH / 64));
        grid_sync();

        // ---- phase 6: clipped EMA update ----
        {
            float total = sqrtf(*gn);
            float clip = fminf(1.0f / (total + 1e-6f), 1.0f);
            float eta = g_eta[c], beta = g_beta[c];
            const int n0 = II * HH, n1 = 2 * II * HH, nt = 2 * II * HH + HH;
            for (int i = bid * 128 + t; i < nt; i += NBLK * 128) {
                if (i < n0) {
                    float ns = eta * g_s0[i] - g_dw0[i] * clip;
                    g_s0[i] = ns;
                    g_w0[i] = beta * g_w0[i] + ns;
                } else if (i < n1) {
                    int j = i - n0;
                    float ns = eta * g_s1[j] - g_dw1[j] * clip;
                    g_s1[j] = ns;
                    g_w1[j] = beta * g_w1[j] + ns;
                } else {
                    int j = i - n1;
                    float ns = eta * g_sln[j] - dln[j] * clip;
                    g_sln[j] = ns;
                    g_ln[j] = beta * g_ln[j] + ns;
                }
            }
        }
        grid_sync();
    }
}

// ---------------- elementwise / reduction kernels ----------------
__global__ __launch_bounds__(256) void init_mem(
    const float* __restrict__ w0, const float* __restrict__ w1, const float* __restrict__ ln)
{
    int n = II * HH;
    for (int i = blockIdx.x * blockDim.x + threadIdx.x; i < n; i += gridDim.x * blockDim.x) {
        g_w0[i] = w0[i]; g_s0[i] = 0.f;
        g_w1[i] = w1[i]; g_s1[i] = 0.f;
        if (i < HH) { g_ln[i] = ln[i]; g_sln[i] = 0.f; }
        if (i < NCH * HH) g_dlnA[i] = 0.f;
        if (i < NCH) g_gnormA[i] = 0.f;
        if (i == 0) { g_bar_cnt = 0u; g_bar_gen = 0u; }
    }
}

__global__ __launch_bounds__(256) void rmsnorm_rows(float* __restrict__ buf, const float* __restrict__ w) {
    int r = blockIdx.x;
    int t = threadIdx.x;
    float4* row = (float4*)(buf + (size_t)r * HH);
    float4 v = row[t];
    float ss = v.x * v.x + v.y * v.y + v.z * v.z + v.w * v.w;
    ss = block_sum(ss);
    float rs = rsqrtf(ss / HH + 1e-6f);
    float4 wv = ((const float4*)w)[t];
    v.x *= rs * wv.x; v.y *= rs * wv.y; v.z *= rs * wv.z; v.w *= rs * wv.w;
    row[t] = v;
}

__global__ __launch_bounds__(256) void gather_all() {
    const int H4 = HH / 4;
    const int per = NN * H4;
    int ntot = NCH * per;
    for (int i = blockIdx.x * blockDim.x + threadIdx.x; i < ntot; i += gridDim.x * blockDim.x) {
        int c = i / per, rem = i - c * per;
        int m = rem / H4, q = rem - m * H4;
        int src = ((m >> 6) * SS + c * CC + (m & 63)) * H4 + q;
        ((float4*)g_kall)[i] = ((const float4*)g_k)[src];
        ((float4*)g_vall)[i] = ((const float4*)g_v)[src];
    }
}

__global__ __launch_bounds__(256) void coeff_dot(
    const float* __restrict__ x, const float* __restrict__ aw,
    const float* __restrict__ tw, const float* __restrict__ ew)
{
    int bc = blockIdx.x;
    int b = bc >> 5, nc = bc & 31;
    const float4* xf = (const float4*)(x + (size_t)(b * SS + nc * CC) * HH);
    const float4* a4 = (const float4*)aw;
    const float4* t4 = (const float4*)tw;
    const float4* e4 = (const float4*)ew;
    const int L4 = CC * HH / 4;
    float sa = 0.f, st = 0.f, se = 0.f;
    for (int i = threadIdx.x; i < L4; i += blockDim.x) {
        float4 xv = xf[i];
        float4 av = a4[i]; sa += xv.x * av.x + xv.y * av.y + xv.z * av.z + xv.w * av.w;
        float4 tv = t4[i]; st += xv.x * tv.x + xv.y * tv.y + xv.z * tv.z + xv.w * tv.w;
        float4 ev = e4[i]; se += xv.x * ev.x + xv.y * ev.y + xv.z * ev.z + xv.w * ev.w;
    }
    sa = block_sum(sa);
    st = block_sum(st);
    se = block_sum(se);
    if (threadIdx.x == 0) { g_dotA[bc] = sa; g_dotT[bc] = st; g_dotE[bc] = se; }
}

__global__ void coeff_finalize() {
    int t = threadIdx.x;
    if (t < BB * NCH) g_theta[t] = sigm(g_dotT[t]) * 0.01f;
    if (t < NCH) {
        float sa = 0.f, se = 0.f;
        for (int b = 0; b < BB; b++) { sa += g_dotA[b * NCH + t]; se += g_dotE[b * NCH + t]; }
        float al = sigm(sa / (float)BB);
        g_beta[t] = 1.f - al;
        g_eta[t] = sigm(se / (float)BB);
    }
}

__global__ __launch_bounds__(256) void final_out(float* __restrict__ out) {
    int r = blockIdx.x, t = threadIdx.x;
    float4 y4 = ((const float4*)(g_y2 + (size_t)r * HH))[t];
    float ss = y4.x * y4.x + y4.y * y4.y + y4.z * y4.z + y4.w * y4.w;
    ss = block_sum(ss);
    float rs = rsqrtf(ss / HH + 1e-6f);
    float4 q4 = ((const float4*)(g_q + (size_t)r * HH))[t];
    float4 l4 = ((const float4*)g_ln)[t];
    float4 o;
    o.x = q4.x + y4.x * rs * l4.x;
    o.y = q4.y + y4.y * rs * l4.y;
    o.z = q4.z + y4.z * rs * l4.z;
    o.w = q4.w + y4.w * rs * l4.w;
    ((float4*)(out + (size_t)r * HH))[t] = o;
}

// ---------------- host launcher ----------------
extern "C" void kernel_launch(void* const* d_in, const int* in_sizes, int n_in,
                              void* d_out, int out_size) {
    const float* x   = (const float*)d_in[0];
    const float* wq  = (const float*)d_in[1];
    const float* wk  = (const float*)d_in[2];
    const float* wv  = (const float*)d_in[3];
    const float* qn  = (const float*)d_in[4];
    const float* kn  = (const float*)d_in[5];
    const float* aw  = (const float*)d_in[6];
    const float* tw  = (const float*)d_in[7];
    const float* ew  = (const float*)d_in[8];
    const float* mw0 = (const float*)d_in[9];
    const float* mw1 = (const float*)d_in[10];
    const float* mln = (const float*)d_in[11];
    float* out = (float*)d_out;

    float *k_, *v_, *q_, *w0_, *w1_, *h2_, *y2_;
    cudaGetSymbolAddress((void**)&k_,  g_k);
    cudaGetSymbolAddress((void**)&v_,  g_v);
    cudaGetSymbolAddress((void**)&q_,  g_q);
    cudaGetSymbolAddress((void**)&w0_, g_w0);
    cudaGetSymbolAddress((void**)&w1_, g_w1);
    cudaGetSymbolAddress((void**)&h2_, g_h2);
    cudaGetSymbolAddress((void**)&y2_, g_y2);

    auto G1 = gemm_tc<128,64,64,32,4,true,true>;   // big parallel NT
    const int S1 = 2 * (128*36 + 64*36) * 4;       // 55296
    const int Sp = 2 * (64*36 + 128*36) * 4;       // 55296 (persistent max = y tiles)
    static int attr_done = 0;
    if (!attr_done) {
        cudaFuncSetAttribute(G1, cudaFuncAttributeMaxDynamicSharedMemorySize, S1);
        cudaFuncSetAttribute(scan_persistent, cudaFuncAttributeMaxDynamicSharedMemorySize, Sp);
        attr_done = 1;
    }

    // ---- init memory params + barrier state ----
    init_mem<<<2048, 256>>>(mw0, mw1, mln);

    // ---- precompute k, v, q ----
    dim3 gKVQ(HH / 64, NROWS / 128);
    G1<<<gKVQ, 128, S1>>>(x, wk, k_, nullptr, nullptr, NROWS, HH, HH, HH, HH, EPI_SILU);
    rmsnorm_rows<<<NROWS, 256>>>(k_, kn);
    G1<<<gKVQ, 128, S1>>>(x, wv, v_, nullptr, nullptr, NROWS, HH, HH, HH, HH, EPI_SILU);
    G1<<<gKVQ, 128, S1>>>(x, wq, q_, nullptr, nullptr, NROWS, HH, HH, HH, HH, EPI_SILU);
    rmsnorm_rows<<<NROWS, 256>>>(q_, qn);
    gather_all<<<2048, 256>>>();

    // ---- adaptive coefficients ----
    coeff_dot<<<BB * NCH, 256>>>(x, aw, tw, ew);
    coeff_finalize<<<1, 256>>>();

    // ---- sequential scan: ONE persistent kernel for all 32 chunks ----
    scan_persistent<<<NBLK, 128, Sp>>>();

    // ---- retrieval with final memory ----
    G1<<<dim3(II / 64, NROWS / 128), 128, S1>>>(q_, w0_, h2_, nullptr, nullptr, NROWS, II, HH, HH, HH, EPI_SILU);
    G1<<<dim3(HH / 64, NROWS / 128), 128, S1>>>(h2_, w1_, y2_, nullptr, nullptr, NROWS, HH, II, II, II, EPI_NONE);
    final_out<<<NROWS, 256>>>(out);
}

// round 14
// speedup vs baseline: 1.3584x; 1.3584x over previous
#include <cuda_runtime.h>
#include <math.h>
#include <stdint.h>

#define BB 8
#define SS 2048
#define HH 1024
#define CC 64
#define NCH 32
#define NN 512      /* BB*CC rows per chunk */
#define II 2048     /* INTER */
#define NROWS 16384 /* BB*SS */
#define H3 3072     /* 3*HH packed kvq width */

#define EPI_NONE 0
#define EPI_SILU 1
#define EPI_SILU_AUX 2
#define EPI_DSILU 3
#define EPI_GRAD 4
#define EPI_GRAD_LN 5

// ---------------- device scratch (no allocation allowed) ----------------
__device__ __align__(16) float g_wkvq[3 * HH * HH];
__device__ __align__(16) float g_kvq[(size_t)NROWS * H3];
__device__ __align__(16) float g_kall[NROWS * HH];
__device__ __align__(16) float g_vall[NROWS * HH];
__device__ __align__(16) float g_w0[II * HH];
__device__ __align__(16) float g_w1[HH * II];
__device__ __align__(16) float g_ln[HH];
__device__ __align__(16) float g_s0[II * HH];
__device__ __align__(16) float g_s1[HH * II];
__device__ __align__(16) float g_sln[HH];
__device__ __align__(16) float g_z[NN * II];
__device__ __align__(16) float g_h[NN * II];
__device__ __align__(16) float g_dz[NN * II];
__device__ __align__(16) float g_y[4 * NN * HH];    /* y split-K partials */
__device__ __align__(16) float g_dy[NN * HH];
__device__ __align__(16) float g_dw0[II * HH];
__device__ __align__(16) float g_dw1[HH * II];
__device__ __align__(16) float g_dlnA[NCH * HH];
__device__ __align__(16) float g_gnormA[NCH];
__device__ __align__(16) float g_h2[NROWS * II];
__device__ __align__(16) float g_y2[NROWS * HH];
__device__ __align__(16) float g_dotA[BB * NCH];
__device__ __align__(16) float g_dotT[BB * NCH];
__device__ __align__(16) float g_dotE[BB * NCH];
__device__ __align__(16) float g_beta[NCH];
__device__ __align__(16) float g_eta[NCH];
__device__ __align__(16) float g_theta[BB * NCH];

// ---------------- helpers ----------------
__device__ __forceinline__ float sigm(float x) { return 1.f / (1.f + expf(-x)); }
__device__ __forceinline__ float silu_f(float x) { return x / (1.f + expf(-x)); }
__device__ __forceinline__ float dsilu_f(float x) {
    float s = 1.f / (1.f + expf(-x));
    return s * (1.f + x * (1.f - s));
}

__device__ __forceinline__ void mma8(float* d, const uint32_t* a, const uint32_t* b) {
    asm volatile(
        "mma.sync.aligned.m16n8k8.row.col.f32.tf32.tf32.f32 "
        "{%0,%1,%2,%3}, {%4,%5,%6,%7}, {%8,%9}, {%0,%1,%2,%3};"
        : "+f"(d[0]), "+f"(d[1]), "+f"(d[2]), "+f"(d[3])
        : "r"(a[0]), "r"(a[1]), "r"(a[2]), "r"(a[3]), "r"(b[0]), "r"(b[1]));
}

#define LDSM_X4(r0, r1, r2, r3, addr) \
    asm volatile("ldmatrix.sync.aligned.m8n8.x4.shared.b16 {%0,%1,%2,%3}, [%4];" \
                 : "=r"(r0), "=r"(r1), "=r"(r2), "=r"(r3) : "r"(addr))

__device__ __forceinline__ void cpa16(float* dst, const float* src) {
    uint32_t d = (uint32_t)__cvta_generic_to_shared(dst);
    asm volatile("cp.async.cg.shared.global [%0], [%1], 16;\n" :: "r"(d), "l"(src));
}
__device__ __forceinline__ void cpa_commit() { asm volatile("cp.async.commit_group;\n"); }

__device__ __forceinline__ float block_sum(float v) {
    __shared__ float sh[32];
    __shared__ float tot;
    int lane = threadIdx.x & 31;
    int w = threadIdx.x >> 5;
#pragma unroll
    for (int o = 16; o > 0; o >>= 1) v += __shfl_xor_sync(0xffffffffu, v, o);
    if (lane == 0) sh[w] = v;
    __syncthreads();
    if (w == 0) {
        float r = (lane < (blockDim.x >> 5)) ? sh[lane] : 0.f;
#pragma unroll
        for (int o = 16; o > 0; o >>= 1) r += __shfl_xor_sync(0xffffffffu, r, o);
        if (lane == 0) tot = r;
    }
    __syncthreads();
    return tot;
}

// ---------------- tf32 tensor-core GEMM body (cp.async + LDSM fragments) ------
// C[M,N] = opA(A) * opB(B).  Raw fp32 inputs; MMA truncates to tf32 (RZ).
template<int BM, int BN, int WM, int WN, int NWARP, bool AT, bool BT>
__device__ __forceinline__ void gemm_body(
    float* sm,
    const float* __restrict__ A, const float* __restrict__ B,
    float* __restrict__ C, float* __restrict__ aux, float* __restrict__ gn,
    int M, int N, int K, int lda, int ldb, int epi, int bx, int by)
{
    constexpr int NT = NWARP * 32;
    constexpr int SA = BM + 8;
    constexpr int SB = BN + 8;
    constexpr int ASZ = AT ? BM * 36 : 32 * SA;
    constexpr int BSZ = BT ? BN * 36 : 32 * SB;
    constexpr int PA = AT ? (BM * 8) / NT : (32 * (BM / 4)) / NT;
    constexpr int PB = BT ? (BN * 8) / NT : (32 * (BN / 4)) / NT;
    constexpr int WGM = BM / WM;
    constexpr int MI = WM / 16, NI = WN / 8;

    float* Ab[2] = { sm, sm + ASZ };
    float* Bb[2] = { sm + 2 * ASZ, sm + 2 * ASZ + BSZ };

    const int t = threadIdx.x;
    const int bm = by * BM, bn = bx * BN;
    const int wid = t >> 5, lane = t & 31;
    const int wm = (wid % WGM) * WM;
    const int wn = (wid / WGM) * WN;
    const int gp = lane >> 2, kq = lane & 3;

    const int lane_row = lane & 7;
    const uint32_t ao = (uint32_t)(((wm + lane_row + ((lane >> 3) & 1) * 8) * 36 +
                                    ((lane >> 4) & 1) * 4) * 4);
    const uint32_t bo = (uint32_t)(((wn + lane_row + ((lane >> 4) & 1) * 8) * 36 +
                                    ((lane >> 3) & 1) * 4) * 4);
    uint32_t AsU[2] = { (uint32_t)__cvta_generic_to_shared(Ab[0]),
                        (uint32_t)__cvta_generic_to_shared(Ab[1]) };
    uint32_t BsU[2] = { (uint32_t)__cvta_generic_to_shared(Bb[0]),
                        (uint32_t)__cvta_generic_to_shared(Bb[1]) };

    float acc[MI][NI][4];
#pragma unroll
    for (int i = 0; i < MI; i++)
#pragma unroll
        for (int j = 0; j < NI; j++)
#pragma unroll
            for (int q = 0; q < 4; q++) acc[i][j][q] = 0.f;

    auto issue = [&](int k0, int buf) {
        float* As = Ab[buf];
        float* Bs = Bb[buf];
#pragma unroll
        for (int p = 0; p < PA; p++) {
            int idx = p * NT + t;
            if constexpr (AT) {
                int row = idx >> 3, seg = idx & 7;
                cpa16(As + row * 36 + seg * 4, A + (size_t)(bm + row) * lda + k0 + seg * 4);
            } else {
                int kk = idx / (BM / 4), mseg = idx % (BM / 4);
                cpa16(As + kk * SA + mseg * 4, A + (size_t)(k0 + kk) * lda + bm + mseg * 4);
            }
        }
#pragma unroll
        for (int p = 0; p < PB; p++) {
            int idx = p * NT + t;
            if constexpr (BT) {
                int row = idx >> 3, seg = idx & 7;
                cpa16(Bs + row * 36 + seg * 4, B + (size_t)(bn + row) * ldb + k0 + seg * 4);
            } else {
                int kk = idx / (BN / 4), nseg = idx % (BN / 4);
                cpa16(Bs + kk * SB + nseg * 4, B + (size_t)(k0 + kk) * ldb + bn + nseg * 4);
            }
        }
        cpa_commit();
    };

    issue(0, 0);
    const int nit = K / 32;
    for (int it = 0; it < nit; it++) {
        if (it + 1 < nit) {
            issue((it + 1) * 32, (it + 1) & 1);
            asm volatile("cp.async.wait_group 1;\n");
        } else {
            asm volatile("cp.async.wait_group 0;\n");
        }
        __syncthreads();
        const int buf = it & 1;
        const float* As = Ab[buf];
        const float* Bs = Bb[buf];
        const uint32_t AsB = AsU[buf], BsB = BsU[buf];
#pragma unroll
        for (int ks = 0; ks < 4; ks++) {
            const int k8 = ks * 8 + kq;
            uint32_t af[MI][4], bf[NI][2];
            if constexpr (AT) {
#pragma unroll
                for (int mi = 0; mi < MI; mi++)
                    LDSM_X4(af[mi][0], af[mi][1], af[mi][2], af[mi][3],
                            AsB + ao + mi * 2304 + ks * 32);
            } else {
#pragma unroll
                for (int mi = 0; mi < MI; mi++) {
                    int r0 = wm + mi * 16 + gp;
                    af[mi][0] = __float_as_uint(As[k8 * SA + r0]);
                    af[mi][1] = __float_as_uint(As[k8 * SA + r0 + 8]);
                    af[mi][2] = __float_as_uint(As[(k8 + 4) * SA + r0]);
                    af[mi][3] = __float_as_uint(As[(k8 + 4) * SA + r0 + 8]);
                }
            }
            if constexpr (BT) {
#pragma unroll
                for (int q = 0; q < NI / 2; q++)
                    LDSM_X4(bf[2 * q][0], bf[2 * q][1], bf[2 * q + 1][0], bf[2 * q + 1][1],
                            BsB + bo + q * 2304 + ks * 32);
            } else {
#pragma unroll
                for (int ni = 0; ni < NI; ni++) {
                    int c0 = wn + ni * 8 + gp;
                    bf[ni][0] = __float_as_uint(Bs[k8 * SB + c0]);
                    bf[ni][1] = __float_as_uint(Bs[(k8 + 4) * SB + c0]);
                }
            }
#pragma unroll
            for (int mi = 0; mi < MI; mi++)
#pragma unroll
                for (int ni = 0; ni < NI; ni++)
                    mma8(acc[mi][ni], af[mi], bf[ni]);
        }
        __syncthreads();
    }

    // epilogue
    float gs = 0.f;
#pragma unroll
    for (int mi = 0; mi < MI; mi++) {
#pragma unroll
        for (int ni = 0; ni < NI; ni++) {
            int r0 = bm + wm + mi * 16 + gp;
            int c = bn + wn + ni * 8 + kq * 2;
            size_t o0 = (size_t)r0 * N + c;
            size_t o1 = (size_t)(r0 + 8) * N + c;
            float2 v0 = make_float2(acc[mi][ni][0], acc[mi][ni][1]);
            float2 v1 = make_float2(acc[mi][ni][2], acc[mi][ni][3]);
            if (epi == EPI_SILU) {
                v0.x = silu_f(v0.x); v0.y = silu_f(v0.y);
                v1.x = silu_f(v1.x); v1.y = silu_f(v1.y);
            } else if (epi == EPI_SILU_AUX) {
                *(float2*)(aux + o0) = v0;
                *(float2*)(aux + o1) = v1;
                v0.x = silu_f(v0.x); v0.y = silu_f(v0.y);
                v1.x = silu_f(v1.x); v1.y = silu_f(v1.y);
            } else if (epi == EPI_DSILU) {
                float2 z0 = *(const float2*)(aux + o0);
                float2 z1 = *(const float2*)(aux + o1);
                v0.x *= dsilu_f(z0.x); v0.y *= dsilu_f(z0.y);
                v1.x *= dsilu_f(z1.x); v1.y *= dsilu_f(z1.y);
            } else if (epi >= EPI_GRAD) {
                gs += v0.x * v0.x + v0.y * v0.y + v1.x * v1.x + v1.y * v1.y;
            }
            *(float2*)(C + o0) = v0;
            *(float2*)(C + o1) = v1;
        }
    }
    if (epi >= EPI_GRAD) {
        gs = block_sum(gs);
        if (t == 0) atomicAdd(gn, gs);
        if (epi == EPI_GRAD_LN && bx == 0 && by == 0) {
            float s = 0.f;
            for (int i = t; i < HH; i += NT) { float d = aux[i]; s += d * d; }
            s = block_sum(s);
            if (t == 0) atomicAdd(gn, s);
        }
    }
}

template<int BM, int BN, int WM, int WN, int NWARP, bool AT, bool BT>
__global__ __launch_bounds__(NWARP * 32) void gemm_tc(
    const float* __restrict__ A, const float* __restrict__ B,
    float* __restrict__ C, float* __restrict__ aux, float* __restrict__ gn,
    int M, int N, int K, int lda, int ldb, int epi)
{
    extern __shared__ float sm[];
    gemm_body<BM, BN, WM, WN, NWARP, AT, BT>(sm, A, B, C, aux, gn, M, N, K, lda, ldb,
                                             epi, blockIdx.x, blockIdx.y);
}

// y split-K=4: yp[s][NN,HH] = h[:, s*512:+512] @ w1[:, s*512:+512]^T
__global__ __launch_bounds__(128) void gemm_y_sk(
    const float* __restrict__ h, const float* __restrict__ w1, float* __restrict__ yp)
{
    extern __shared__ float sm[];
    int s = blockIdx.z;
    gemm_body<64, 128, 32, 64, 4, true, true>(
        sm, h + s * (II / 4), w1 + s * (II / 4), yp + (size_t)s * NN * HH,
        nullptr, nullptr, NN, HH, II / 4, II, II, EPI_NONE, blockIdx.x, blockIdx.y);
}

// fused: z==0 (by<8): dz = (dy @ w1) * silu'(z)   64x64 tiles, grid (32,8)
//        z==1       : dw1 = dy^T @ h + grad sumsq  64x64 tiles, grid (32,16)
__global__ __launch_bounds__(128) void fused_dz_dw1(
    const float* __restrict__ dy, const float* __restrict__ w1,
    float* __restrict__ dz, float* __restrict__ z,
    const float* __restrict__ h, float* __restrict__ dw1, float* __restrict__ gn)
{
    extern __shared__ float sm[];
    if (blockIdx.z == 0) {
        if (blockIdx.y < 8)
            gemm_body<64, 64, 32, 32, 4, true, false>(
                sm, dy, w1, dz, z, nullptr, NN, II, HH, HH, II, EPI_DSILU,
                blockIdx.x, blockIdx.y);
    } else {
        gemm_body<64, 64, 32, 32, 4, false, false>(
            sm, dy, h, dw1, nullptr, gn, HH, II, NN, HH, II, EPI_GRAD,
            blockIdx.x, blockIdx.y);
    }
}

// ---------------- elementwise / reduction kernels ----------------
__global__ __launch_bounds__(256) void init_mem(
    const float* __restrict__ w0, const float* __restrict__ w1, const float* __restrict__ ln,
    const float* __restrict__ wk, const float* __restrict__ wv, const float* __restrict__ wq)
{
    int n = II * HH;
    for (int i = blockIdx.x * blockDim.x + threadIdx.x; i < n; i += gridDim.x * blockDim.x) {
        g_w0[i] = w0[i]; g_s0[i] = 0.f;
        g_w1[i] = w1[i]; g_s1[i] = 0.f;
        if (i < HH * HH) {
            g_wkvq[i] = wk[i];
            g_wkvq[HH * HH + i] = wv[i];
            g_wkvq[2 * HH * HH + i] = wq[i];
        }
        if (i < HH) { g_ln[i] = ln[i]; g_sln[i] = 0.f; }
        if (i < NCH * HH) g_dlnA[i] = 0.f;
        if (i < NCH) g_gnormA[i] = 0.f;
    }
}

// fused rmsnorm over k rows (cols 0..1023) and q rows (cols 2048..3071) of g_kvq
__global__ __launch_bounds__(256) void rmsnorm_kq(const float* __restrict__ kn,
                                                  const float* __restrict__ qn) {
    int r = blockIdx.x;
    int t = threadIdx.x;
    float* rowp;
    const float* w;
    if (r < NROWS) { rowp = g_kvq + (size_t)r * H3; w = kn; }
    else { rowp = g_kvq + (size_t)(r - NROWS) * H3 + 2 * HH; w = qn; }
    float4* row = (float4*)rowp;
    float4 v = row[t];
    float ss = v.x * v.x + v.y * v.y + v.z * v.z + v.w * v.w;
    ss = block_sum(ss);
    float rs = rsqrtf(ss / HH + 1e-6f);
    float4 wv = ((const float4*)w)[t];
    v.x *= rs * wv.x; v.y *= rs * wv.y; v.z *= rs * wv.z; v.w *= rs * wv.w;
    row[t] = v;
}

__global__ __launch_bounds__(256) void gather_all() {
    const int H4 = HH / 4;       // 256 float4 per HH row
    const int W4 = H3 / 4;       // 768 float4 per packed row
    const int per = NN * H4;
    int ntot = NCH * per;
    for (int i = blockIdx.x * blockDim.x + threadIdx.x; i < ntot; i += gridDim.x * blockDim.x) {
        int c = i / per, rem = i - c * per;
        int m = rem / H4, q = rem - m * H4;
        int rr = (m >> 6) * SS + c * CC + (m & 63);
        ((float4*)g_kall)[i] = ((const float4*)g_kvq)[(size_t)rr * W4 + q];
        ((float4*)g_vall)[i] = ((const float4*)g_kvq)[(size_t)rr * W4 + H4 + q];
    }
}

__global__ __launch_bounds__(256) void coeff_dot(
    const float* __restrict__ x, const float* __restrict__ aw,
    const float* __restrict__ tw, const float* __restrict__ ew)
{
    int bc = blockIdx.x;
    int b = bc >> 5, nc = bc & 31;
    const float4* xf = (const float4*)(x + (size_t)(b * SS + nc * CC) * HH);
    const float4* a4 = (const float4*)aw;
    const float4* t4 = (const float4*)tw;
    const float4* e4 = (const float4*)ew;
    const int L4 = CC * HH / 4;
    float sa = 0.f, st = 0.f, se = 0.f;
    for (int i = threadIdx.x; i < L4; i += blockDim.x) {
        float4 xv = xf[i];
        float4 av = a4[i]; sa += xv.x * av.x + xv.y * av.y + xv.z * av.z + xv.w * av.w;
        float4 tv = t4[i]; st += xv.x * tv.x + xv.y * tv.y + xv.z * tv.z + xv.w * tv.w;
        float4 ev = e4[i]; se += xv.x * ev.x + xv.y * ev.y + xv.z * ev.z + xv.w * ev.w;
    }
    sa = block_sum(sa);
    st = block_sum(st);
    se = block_sum(se);
    if (threadIdx.x == 0) { g_dotA[bc] = sa; g_dotT[bc] = st; g_dotE[bc] = se; }
}

__global__ void coeff_finalize() {
    int t = threadIdx.x;
    if (t < BB * NCH) g_theta[t] = sigm(g_dotT[t]) * 0.01f;
    if (t < NCH) {
        float sa = 0.f, se = 0.f;
        for (int b = 0; b < BB; b++) { sa += g_dotA[b * NCH + t]; se += g_dotE[b * NCH + t]; }
        float al = sigm(sa / (float)BB);
        g_beta[t] = 1.f - al;
        g_eta[t] = sigm(se / (float)BB);
    }
}

// backward through rmsnorm + residual + weighted MSE; combines 4 split-K y parts
__global__ __launch_bounds__(256) void chunk_bwd_y(int c) {
    int r = blockIdx.x;
    int t = threadIdx.x;
    int b = r >> 6;
    const float* kc = g_kall + (size_t)c * NN * HH;
    const float* vc = g_vall + (size_t)c * NN * HH;
    float4 y0 = ((const float4*)(g_y + (size_t)r * HH))[t];
    float4 y1 = ((const float4*)(g_y + (size_t)(NN + r) * HH))[t];
    float4 y2 = ((const float4*)(g_y + (size_t)(2 * NN + r) * HH))[t];
    float4 y3 = ((const float4*)(g_y + (size_t)(3 * NN + r) * HH))[t];
    float4 y4;
    y4.x = (y0.x + y1.x) + (y2.x + y3.x);
    y4.y = (y0.y + y1.y) + (y2.y + y3.y);
    y4.z = (y0.z + y1.z) + (y2.z + y3.z);
    y4.w = (y0.w + y1.w) + (y2.w + y3.w);
    float ss = y4.x * y4.x + y4.y * y4.y + y4.z * y4.z + y4.w * y4.w;
    ss = block_sum(ss);
    float rs = rsqrtf(ss / HH + 1e-6f);
    float th = g_theta[b * NCH + c];
    float scale = 2.f * th / ((float)NN * (float)HH);
    float4 k4 = ((const float4*)(kc + (size_t)r * HH))[t];
    float4 v4 = ((const float4*)(vc + (size_t)r * HH))[t];
    float4 l4 = ((const float4*)g_ln)[t];
    float4 gg;
    gg.x = scale * (k4.x + y4.x * rs * l4.x - v4.x);
    gg.y = scale * (k4.y + y4.y * rs * l4.y - v4.y);
    gg.z = scale * (k4.z + y4.z * rs * l4.z - v4.z);
    gg.w = scale * (k4.w + y4.w * rs * l4.w - v4.w);
    float sv = gg.x * l4.x * y4.x + gg.y * l4.y * y4.y + gg.z * l4.z * y4.z + gg.w * l4.w * y4.w;
    sv = block_sum(sv);
    float c3 = rs * rs * rs * sv / (float)HH;
    float4 dy;
    dy.x = rs * gg.x * l4.x - c3 * y4.x;
    dy.y = rs * gg.y * l4.y - c3 * y4.y;
    dy.z = rs * gg.z * l4.z - c3 * y4.z;
    dy.w = rs * gg.w * l4.w - c3 * y4.w;
    ((float4*)(g_dy + (size_t)r * HH))[t] = dy;
    float* dln = g_dlnA + c * HH;
    atomicAdd(&dln[t * 4 + 0], gg.x * y4.x * rs);
    atomicAdd(&dln[t * 4 + 1], gg.y * y4.y * rs);
    atomicAdd(&dln[t * 4 + 2], gg.z * y4.z * rs);
    atomicAdd(&dln[t * 4 + 3], gg.w * y4.w * rs);
}

__global__ __launch_bounds__(256) void update_params(int c) {
    float total = sqrtf(g_gnormA[c]);
    float clip = fminf(1.0f / (total + 1e-6f), 1.0f);
    float eta = g_eta[c], beta = g_beta[c];
    const float* dln = g_dlnA + c * HH;
    const int n0 = II * HH, n1 = 2 * II * HH, nt = 2 * II * HH + HH;
    for (int i = blockIdx.x * blockDim.x + threadIdx.x; i < nt; i += gridDim.x * blockDim.x) {
        if (i < n0) {
            float ns = eta * g_s0[i] - g_dw0[i] * clip;
            g_s0[i] = ns;
            g_w0[i] = beta * g_w0[i] + ns;
        } else if (i < n1) {
            int j = i - n0;
            float ns = eta * g_s1[j] - g_dw1[j] * clip;
            g_s1[j] = ns;
            g_w1[j] = beta * g_w1[j] + ns;
        } else {
            int j = i - n1;
            float ns = eta * g_sln[j] - dln[j] * clip;
            g_sln[j] = ns;
            g_ln[j] = beta * g_ln[j] + ns;
        }
    }
}

__global__ __launch_bounds__(256) void final_out(float* __restrict__ out) {
    int r = blockIdx.x, t = threadIdx.x;
    float4 y4 = ((const float4*)(g_y2 + (size_t)r * HH))[t];
    float ss = y4.x * y4.x + y4.y * y4.y + y4.z * y4.z + y4.w * y4.w;
    ss = block_sum(ss);
    float rs = rsqrtf(ss / HH + 1e-6f);
    float4 q4 = ((const float4*)(g_kvq + (size_t)r * H3 + 2 * HH))[t];
    float4 l4 = ((const float4*)g_ln)[t];
    float4 o;
    o.x = q4.x + y4.x * rs * l4.x;
    o.y = q4.y + y4.y * rs * l4.y;
    o.z = q4.z + y4.z * rs * l4.z;
    o.w = q4.w + y4.w * rs * l4.w;
    ((float4*)(out + (size_t)r * HH))[t] = o;
}

// ---------------- host launcher ----------------
extern "C" void kernel_launch(void* const* d_in, const int* in_sizes, int n_in,
                              void* d_out, int out_size) {
    const float* x   = (const float*)d_in[0];
    const float* wq  = (const float*)d_in[1];
    const float* wk  = (const float*)d_in[2];
    const float* wv  = (const float*)d_in[3];
    const float* qn  = (const float*)d_in[4];
    const float* kn  = (const float*)d_in[5];
    const float* aw  = (const float*)d_in[6];
    const float* tw  = (const float*)d_in[7];
    const float* ew  = (const float*)d_in[8];
    const float* mw0 = (const float*)d_in[9];
    const float* mw1 = (const float*)d_in[10];
    const float* mln = (const float*)d_in[11];
    float* out = (float*)d_out;

    float *wkvq_, *kvq_, *w0_, *w1_, *kall_, *z_, *h_, *y_, *dy_, *dz_;
    float *dw0_, *dw1_, *dlnA_, *gnA_, *h2_, *y2_;
    cudaGetSymbolAddress((void**)&wkvq_, g_wkvq);
    cudaGetSymbolAddress((void**)&kvq_,  g_kvq);
    cudaGetSymbolAddress((void**)&w0_,   g_w0);
    cudaGetSymbolAddress((void**)&w1_,   g_w1);
    cudaGetSymbolAddress((void**)&kall_, g_kall);
    cudaGetSymbolAddress((void**)&z_,    g_z);
    cudaGetSymbolAddress((void**)&h_,    g_h);
    cudaGetSymbolAddress((void**)&y_,    g_y);
    cudaGetSymbolAddress((void**)&dy_,   g_dy);
    cudaGetSymbolAddress((void**)&dz_,   g_dz);
    cudaGetSymbolAddress((void**)&dw0_,  g_dw0);
    cudaGetSymbolAddress((void**)&dw1_,  g_dw1);
    cudaGetSymbolAddress((void**)&dlnA_, g_dlnA);
    cudaGetSymbolAddress((void**)&gnA_,  g_gnormA);
    cudaGetSymbolAddress((void**)&h2_,   g_h2);
    cudaGetSymbolAddress((void**)&y2_,   g_y2);

    auto G1 = gemm_tc<128,64,64,32,4,true,true>;   // big parallel NT
    auto Gz = gemm_tc<64,64,32,32,4,true,true>;    // z = kc @ w0^T (direct)
    auto Gw = gemm_tc<64,64,32,32,4,false,false>;  // TN dw0
    const int S1 = 2 * (128*36 + 64*36) * 4;       // 55296
    const int Sz = 2 * (64*36 + 64*36) * 4;        // 36864
    const int Sy = 2 * (64*36 + 128*36) * 4;       // 55296
    const int Sw = 2 * (32*72 + 32*72) * 4;        // 36864
    const int Sf = 36864;                          // fused max (both 64x64 bodies)
    static int attr_done = 0;
    if (!attr_done) {
        cudaFuncSetAttribute(G1, cudaFuncAttributeMaxDynamicSharedMemorySize, S1);
        cudaFuncSetAttribute(Gz, cudaFuncAttributeMaxDynamicSharedMemorySize, Sz);
        cudaFuncSetAttribute(gemm_y_sk, cudaFuncAttributeMaxDynamicSharedMemorySize, Sy);
        cudaFuncSetAttribute(Gw, cudaFuncAttributeMaxDynamicSharedMemorySize, Sw);
        cudaFuncSetAttribute(fused_dz_dw1, cudaFuncAttributeMaxDynamicSharedMemorySize, Sf);
        attr_done = 1;
    }

    // ---- init memory params + pack kvq weights ----
    init_mem<<<2048, 256>>>(mw0, mw1, mln, wk, wv, wq);

    // ---- fused k|v|q projection: one GEMM, N=3072 ----
    G1<<<dim3(H3 / 64, NROWS / 128), 128, S1>>>(x, wkvq_, kvq_, nullptr, nullptr,
                                                NROWS, H3, HH, HH, HH, EPI_SILU);
    // fused rmsnorm over k rows and q rows
    rmsnorm_kq<<<2 * NROWS, 256>>>(kn, qn);
    gather_all<<<2048, 256>>>();

    // ---- adaptive coefficients ----
    coeff_dot<<<BB * NCH, 256>>>(x, aw, tw, ew);
    coeff_finalize<<<1, 256>>>();

    // ---- sequential scan over chunks (6 launches/chunk) ----
    for (int c = 0; c < NCH; c++) {
        const float* kc = kall_ + (size_t)c * NN * HH;
        // z = kc @ w0^T (direct K=1024), h = silu(z), aux z — 256 blocks
        Gz<<<dim3(II / 64, NN / 64), 128, Sz>>>(kc, w0_, h_, z_, nullptr, NN, II, HH, HH, HH, EPI_SILU_AUX);
        // y partials (split-K=4, 256 blocks; combined inside chunk_bwd_y)
        gemm_y_sk<<<dim3(HH / 128, NN / 64, 4), 128, Sy>>>(h_, w1_, y_);
        // backward through residual + rmsnorm + MSE (sums 4 y partials, dln atomics)
        chunk_bwd_y<<<NN, 256>>>(c);
        // dz = (dy @ w1)*dsilu(z) (direct) || dw1 = dy^T @ h (+grad) — one launch
        fused_dz_dw1<<<dim3(32, 16, 2), 128, Sf>>>(dy_, w1_, dz_, z_, h_, dw1_, gnA_ + c);
        // dw0 = dz^T @ kc (+grad sumsq + dln^2) — 512 blocks
        Gw<<<dim3(HH / 64, II / 64), 128, Sw>>>(dz_, kc, dw0_, dlnA_ + c * HH, gnA_ + c, II, HH, NN, II, HH, EPI_GRAD_LN);
        // clipped EMA update
        update_params<<<1024, 256>>>(c);
    }

    // ---- retrieval with final memory (q = g_kvq cols 2048.., lda=3072) ----
    G1<<<dim3(II / 64, NROWS / 128), 128, S1>>>(kvq_ + 2 * HH, w0_, h2_, nullptr, nullptr,
                                               NROWS, II, HH, H3, HH, EPI_SILU);
    G1<<<dim3(HH / 64, NROWS / 128), 128, S1>>>(h2_, w1_, y2_, nullptr, nullptr,
                                               NROWS, HH, II, II, II, EPI_NONE);
    final_out<<<NROWS, 256>>>(out);
}

// round 15
// speedup vs baseline: 1.4365x; 1.0576x over previous
#include <cuda_runtime.h>
#include <cuda_fp16.h>
#include <math.h>
#include <stdint.h>

#define BB 8
#define SS 2048
#define HH 1024
#define CC 64
#define NCH 32
#define NN 512      /* BB*CC rows per chunk */
#define II 2048     /* INTER */
#define NROWS 16384 /* BB*SS */
#define H3 3072     /* 3*HH packed kvq width */

#define EPI_NONE 0
#define EPI_SILU 1
#define EPI_SILU_AUX 2
#define EPI_DSILU 3
#define EPI_GRAD 4
#define EPI_GRAD_LN 5

// fp16 GEMM epilogues
#define HEPI_NONE 0
#define HEPI_SILU_F 1
#define HEPI_SILU_H 2

// ---------------- device scratch (no allocation allowed) ----------------
__device__ __align__(16) __half g_x16[NROWS * HH];
__device__ __align__(16) __half g_wkvq16[3 * HH * HH];
__device__ __align__(16) __half g_q16[NROWS * HH];
__device__ __align__(16) __half g_w016[II * HH];
__device__ __align__(16) __half g_w116[HH * II];
__device__ __align__(16) __half g_h2h[(size_t)NROWS * II];
__device__ __align__(16) float g_kvq[(size_t)NROWS * H3];
__device__ __align__(16) float g_kall[NROWS * HH];
__device__ __align__(16) float g_vall[NROWS * HH];
__device__ __align__(16) float g_w0[II * HH];
__device__ __align__(16) float g_w1[HH * II];
__device__ __align__(16) float g_ln[HH];
__device__ __align__(16) float g_s0[II * HH];
__device__ __align__(16) float g_s1[HH * II];
__device__ __align__(16) float g_sln[HH];
__device__ __align__(16) float g_z[NN * II];
__device__ __align__(16) float g_h[NN * II];
__device__ __align__(16) float g_dz[NN * II];
__device__ __align__(16) float g_y[4 * NN * HH];
__device__ __align__(16) float g_dy[NN * HH];
__device__ __align__(16) float g_dw0[II * HH];
__device__ __align__(16) float g_dw1[HH * II];
__device__ __align__(16) float g_dlnA[NCH * HH];
__device__ __align__(16) float g_gnormA[NCH];
__device__ __align__(16) float g_y2[NROWS * HH];
__device__ __align__(16) float g_dotA[BB * NCH];
__device__ __align__(16) float g_dotT[BB * NCH];
__device__ __align__(16) float g_dotE[BB * NCH];
__device__ __align__(16) float g_beta[NCH];
__device__ __align__(16) float g_eta[NCH];
__device__ __align__(16) float g_theta[BB * NCH];

// ---------------- helpers ----------------
__device__ __forceinline__ float sigm(float x) { return 1.f / (1.f + expf(-x)); }
__device__ __forceinline__ float silu_f(float x) { return x / (1.f + expf(-x)); }
__device__ __forceinline__ float dsilu_f(float x) {
    float s = 1.f / (1.f + expf(-x));
    return s * (1.f + x * (1.f - s));
}

__device__ __forceinline__ void mma8(float* d, const uint32_t* a, const uint32_t* b) {
    asm volatile(
        "mma.sync.aligned.m16n8k8.row.col.f32.tf32.tf32.f32 "
        "{%0,%1,%2,%3}, {%4,%5,%6,%7}, {%8,%9}, {%0,%1,%2,%3};"
        : "+f"(d[0]), "+f"(d[1]), "+f"(d[2]), "+f"(d[3])
        : "r"(a[0]), "r"(a[1]), "r"(a[2]), "r"(a[3]), "r"(b[0]), "r"(b[1]));
}

__device__ __forceinline__ void mma16(float* d, const uint32_t* a, const uint32_t* b) {
    asm volatile(
        "mma.sync.aligned.m16n8k16.row.col.f32.f16.f16.f32 "
        "{%0,%1,%2,%3}, {%4,%5,%6,%7}, {%8,%9}, {%0,%1,%2,%3};"
        : "+f"(d[0]), "+f"(d[1]), "+f"(d[2]), "+f"(d[3])
        : "r"(a[0]), "r"(a[1]), "r"(a[2]), "r"(a[3]), "r"(b[0]), "r"(b[1]));
}

#define LDSM_X4(r0, r1, r2, r3, addr) \
    asm volatile("ldmatrix.sync.aligned.m8n8.x4.shared.b16 {%0,%1,%2,%3}, [%4];" \
                 : "=r"(r0), "=r"(r1), "=r"(r2), "=r"(r3) : "r"(addr))

__device__ __forceinline__ void cpa16(float* dst, const float* src) {
    uint32_t d = (uint32_t)__cvta_generic_to_shared(dst);
    asm volatile("cp.async.cg.shared.global [%0], [%1], 16;\n" :: "r"(d), "l"(src));
}
__device__ __forceinline__ void cpa16h(__half* dst, const __half* src) {
    uint32_t d = (uint32_t)__cvta_generic_to_shared(dst);
    asm volatile("cp.async.cg.shared.global [%0], [%1], 16;\n" :: "r"(d), "l"(src));
}
__device__ __forceinline__ void cpa_commit() { asm volatile("cp.async.commit_group;\n"); }

__device__ __forceinline__ float block_sum(float v) {
    __shared__ float sh[32];
    __shared__ float tot;
    int lane = threadIdx.x & 31;
    int w = threadIdx.x >> 5;
#pragma unroll
    for (int o = 16; o > 0; o >>= 1) v += __shfl_xor_sync(0xffffffffu, v, o);
    if (lane == 0) sh[w] = v;
    __syncthreads();
    if (w == 0) {
        float r = (lane < (blockDim.x >> 5)) ? sh[lane] : 0.f;
#pragma unroll
        for (int o = 16; o > 0; o >>= 1) r += __shfl_xor_sync(0xffffffffu, r, o);
        if (lane == 0) tot = r;
    }
    __syncthreads();
    return tot;
}

// ---------------- fp16 tensor-core GEMM (NT, 128x64 block, 64x32 warp) --------
// C[M,N] = A(MxK) * B(NxK)^T, fp16 inputs, fp32 accumulate.
__global__ __launch_bounds__(128) void gemm_h16(
    const __half* __restrict__ A, const __half* __restrict__ B,
    float* __restrict__ Cf, __half* __restrict__ Ch,
    int M, int N, int K, int lda, int ldb, int epi)
{
    extern __shared__ __half smh[];
    constexpr int AR = 40;                 // halfs per staged row (80B, 16B-aligned)
    constexpr int ASZ = 128 * AR;
    constexpr int BSZ = 64 * AR;
    __half* Ab[2] = { smh, smh + ASZ };
    __half* Bb[2] = { smh + 2 * ASZ, smh + 2 * ASZ + BSZ };

    const int t = threadIdx.x;
    const int bm = blockIdx.y * 128, bn = blockIdx.x * 64;
    const int wid = t >> 5, lane = t & 31;
    const int wm = (wid & 1) * 64;
    const int wn = (wid >> 1) * 32;
    const int gp = lane >> 2, kq = lane & 3;

    // ldmatrix lane byte offsets
    const uint32_t aoh = (uint32_t)(((wm + (lane & 15)) * AR + ((lane >> 4) & 1) * 8) * 2);
    const uint32_t boh = (uint32_t)(((wn + (lane & 7) + ((lane >> 4) & 1) * 8) * AR +
                                     ((lane >> 3) & 1) * 8) * 2);
    uint32_t AsU[2] = { (uint32_t)__cvta_generic_to_shared(Ab[0]),
                        (uint32_t)__cvta_generic_to_shared(Ab[1]) };
    uint32_t BsU[2] = { (uint32_t)__cvta_generic_to_shared(Bb[0]),
                        (uint32_t)__cvta_generic_to_shared(Bb[1]) };

    float acc[4][4][4];
#pragma unroll
    for (int i = 0; i < 4; i++)
#pragma unroll
        for (int j = 0; j < 4; j++)
#pragma unroll
            for (int q = 0; q < 4; q++) acc[i][j][q] = 0.f;

    auto issue = [&](int k0, int buf) {
        __half* As = Ab[buf];
        __half* Bs = Bb[buf];
#pragma unroll
        for (int p = 0; p < 4; p++) {
            int idx = p * 128 + t;
            int row = idx >> 2, seg = idx & 3;
            cpa16h(As + row * AR + seg * 8, A + (size_t)(bm + row) * lda + k0 + seg * 8);
        }
#pragma unroll
        for (int p = 0; p < 2; p++) {
            int idx = p * 128 + t;
            int row = idx >> 2, seg = idx & 3;
            cpa16h(Bs + row * AR + seg * 8, B + (size_t)(bn + row) * ldb + k0 + seg * 8);
        }
        cpa_commit();
    };

    issue(0, 0);
    const int nit = K / 32;
    for (int it = 0; it < nit; it++) {
        if (it + 1 < nit) {
            issue((it + 1) * 32, (it + 1) & 1);
            asm volatile("cp.async.wait_group 1;\n");
        } else {
            asm volatile("cp.async.wait_group 0;\n");
        }
        __syncthreads();
        const int buf = it & 1;
        const uint32_t AsB = AsU[buf], BsB = BsU[buf];
#pragma unroll
        for (int ks = 0; ks < 2; ks++) {
            uint32_t af[4][4], bf[4][2];
#pragma unroll
            for (int mi = 0; mi < 4; mi++)
                LDSM_X4(af[mi][0], af[mi][1], af[mi][2], af[mi][3],
                        AsB + aoh + mi * (16 * AR * 2) + ks * 32);
#pragma unroll
            for (int q = 0; q < 2; q++)
                LDSM_X4(bf[2 * q][0], bf[2 * q][1], bf[2 * q + 1][0], bf[2 * q + 1][1],
                        BsB + boh + q * (16 * AR * 2) + ks * 32);
#pragma unroll
            for (int mi = 0; mi < 4; mi++)
#pragma unroll
                for (int ni = 0; ni < 4; ni++)
                    mma16(acc[mi][ni], af[mi], bf[ni]);
        }
        __syncthreads();
    }

    // epilogue
#pragma unroll
    for (int mi = 0; mi < 4; mi++) {
#pragma unroll
        for (int ni = 0; ni < 4; ni++) {
            int r0 = bm + wm + mi * 16 + gp;
            int c = bn + wn + ni * 8 + kq * 2;
            size_t o0 = (size_t)r0 * N + c;
            size_t o1 = (size_t)(r0 + 8) * N + c;
            float2 v0 = make_float2(acc[mi][ni][0], acc[mi][ni][1]);
            float2 v1 = make_float2(acc[mi][ni][2], acc[mi][ni][3]);
            if (epi == HEPI_SILU_F) {
                v0.x = silu_f(v0.x); v0.y = silu_f(v0.y);
                v1.x = silu_f(v1.x); v1.y = silu_f(v1.y);
                *(float2*)(Cf + o0) = v0;
                *(float2*)(Cf + o1) = v1;
            } else if (epi == HEPI_SILU_H) {
                *(__half2*)(Ch + o0) = __floats2half2_rn(silu_f(v0.x), silu_f(v0.y));
                *(__half2*)(Ch + o1) = __floats2half2_rn(silu_f(v1.x), silu_f(v1.y));
            } else {
                *(float2*)(Cf + o0) = v0;
                *(float2*)(Cf + o1) = v1;
            }
        }
    }
}

// ---------------- tf32 tensor-core GEMM body (cp.async + LDSM fragments) ------
template<int BM, int BN, int WM, int WN, int NWARP, bool AT, bool BT>
__device__ __forceinline__ void gemm_body(
    float* sm,
    const float* __restrict__ A, const float* __restrict__ B,
    float* __restrict__ C, float* __restrict__ aux, float* __restrict__ gn,
    int M, int N, int K, int lda, int ldb, int epi, int bx, int by)
{
    constexpr int NT = NWARP * 32;
    constexpr int SA = BM + 8;
    constexpr int SB = BN + 8;
    constexpr int ASZ = AT ? BM * 36 : 32 * SA;
    constexpr int BSZ = BT ? BN * 36 : 32 * SB;
    constexpr int PA = AT ? (BM * 8) / NT : (32 * (BM / 4)) / NT;
    constexpr int PB = BT ? (BN * 8) / NT : (32 * (BN / 4)) / NT;
    constexpr int WGM = BM / WM;
    constexpr int MI = WM / 16, NI = WN / 8;

    float* Ab[2] = { sm, sm + ASZ };
    float* Bb[2] = { sm + 2 * ASZ, sm + 2 * ASZ + BSZ };

    const int t = threadIdx.x;
    const int bm = by * BM, bn = bx * BN;
    const int wid = t >> 5, lane = t & 31;
    const int wm = (wid % WGM) * WM;
    const int wn = (wid / WGM) * WN;
    const int gp = lane >> 2, kq = lane & 3;

    const int lane_row = lane & 7;
    const uint32_t ao = (uint32_t)(((wm + lane_row + ((lane >> 3) & 1) * 8) * 36 +
                                    ((lane >> 4) & 1) * 4) * 4);
    const uint32_t bo = (uint32_t)(((wn + lane_row + ((lane >> 4) & 1) * 8) * 36 +
                                    ((lane >> 3) & 1) * 4) * 4);
    uint32_t AsU[2] = { (uint32_t)__cvta_generic_to_shared(Ab[0]),
                        (uint32_t)__cvta_generic_to_shared(Ab[1]) };
    uint32_t BsU[2] = { (uint32_t)__cvta_generic_to_shared(Bb[0]),
                        (uint32_t)__cvta_generic_to_shared(Bb[1]) };

    float acc[MI][NI][4];
#pragma unroll
    for (int i = 0; i < MI; i++)
#pragma unroll
        for (int j = 0; j < NI; j++)
#pragma unroll
            for (int q = 0; q < 4; q++) acc[i][j][q] = 0.f;

    auto issue = [&](int k0, int buf) {
        float* As = Ab[buf];
        float* Bs = Bb[buf];
#pragma unroll
        for (int p = 0; p < PA; p++) {
            int idx = p * NT + t;
            if constexpr (AT) {
                int row = idx >> 3, seg = idx & 7;
                cpa16(As + row * 36 + seg * 4, A + (size_t)(bm + row) * lda + k0 + seg * 4);
            } else {
                int kk = idx / (BM / 4), mseg = idx % (BM / 4);
                cpa16(As + kk * SA + mseg * 4, A + (size_t)(k0 + kk) * lda + bm + mseg * 4);
            }
        }
#pragma unroll
        for (int p = 0; p < PB; p++) {
            int idx = p * NT + t;
            if constexpr (BT) {
                int row = idx >> 3, seg = idx & 7;
                cpa16(Bs + row * 36 + seg * 4, B + (size_t)(bn + row) * ldb + k0 + seg * 4);
            } else {
                int kk = idx / (BN / 4), nseg = idx % (BN / 4);
                cpa16(Bs + kk * SB + nseg * 4, B + (size_t)(k0 + kk) * ldb + bn + nseg * 4);
            }
        }
        cpa_commit();
    };

    issue(0, 0);
    const int nit = K / 32;
    for (int it = 0; it < nit; it++) {
        if (it + 1 < nit) {
            issue((it + 1) * 32, (it + 1) & 1);
            asm volatile("cp.async.wait_group 1;\n");
        } else {
            asm volatile("cp.async.wait_group 0;\n");
        }
        __syncthreads();
        const int buf = it & 1;
        const float* As = Ab[buf];
        const float* Bs = Bb[buf];
        const uint32_t AsB = AsU[buf], BsB = BsU[buf];
#pragma unroll
        for (int ks = 0; ks < 4; ks++) {
            const int k8 = ks * 8 + kq;
            uint32_t af[MI][4], bf[NI][2];
            if constexpr (AT) {
#pragma unroll
                for (int mi = 0; mi < MI; mi++)
                    LDSM_X4(af[mi][0], af[mi][1], af[mi][2], af[mi][3],
                            AsB + ao + mi * 2304 + ks * 32);
            } else {
#pragma unroll
                for (int mi = 0; mi < MI; mi++) {
                    int r0 = wm + mi * 16 + gp;
                    af[mi][0] = __float_as_uint(As[k8 * SA + r0]);
                    af[mi][1] = __float_as_uint(As[k8 * SA + r0 + 8]);
                    af[mi][2] = __float_as_uint(As[(k8 + 4) * SA + r0]);
                    af[mi][3] = __float_as_uint(As[(k8 + 4) * SA + r0 + 8]);
                }
            }
            if constexpr (BT) {
#pragma unroll
                for (int q = 0; q < NI / 2; q++)
                    LDSM_X4(bf[2 * q][0], bf[2 * q][1], bf[2 * q + 1][0], bf[2 * q + 1][1],
                            BsB + bo + q * 2304 + ks * 32);
            } else {
#pragma unroll
                for (int ni = 0; ni < NI; ni++) {
                    int c0 = wn + ni * 8 + gp;
                    bf[ni][0] = __float_as_uint(Bs[k8 * SB + c0]);
                    bf[ni][1] = __float_as_uint(Bs[(k8 + 4) * SB + c0]);
                }
            }
#pragma unroll
            for (int mi = 0; mi < MI; mi++)
#pragma unroll
                for (int ni = 0; ni < NI; ni++)
                    mma8(acc[mi][ni], af[mi], bf[ni]);
        }
        __syncthreads();
    }

    // epilogue
    float gs = 0.f;
#pragma unroll
    for (int mi = 0; mi < MI; mi++) {
#pragma unroll
        for (int ni = 0; ni < NI; ni++) {
            int r0 = bm + wm + mi * 16 + gp;
            int c = bn + wn + ni * 8 + kq * 2;
            size_t o0 = (size_t)r0 * N + c;
            size_t o1 = (size_t)(r0 + 8) * N + c;
            float2 v0 = make_float2(acc[mi][ni][0], acc[mi][ni][1]);
            float2 v1 = make_float2(acc[mi][ni][2], acc[mi][ni][3]);
            if (epi == EPI_SILU) {
                v0.x = silu_f(v0.x); v0.y = silu_f(v0.y);
                v1.x = silu_f(v1.x); v1.y = silu_f(v1.y);
            } else if (epi == EPI_SILU_AUX) {
                *(float2*)(aux + o0) = v0;
                *(float2*)(aux + o1) = v1;
                v0.x = silu_f(v0.x); v0.y = silu_f(v0.y);
                v1.x = silu_f(v1.x); v1.y = silu_f(v1.y);
            } else if (epi == EPI_DSILU) {
                float2 z0 = *(const float2*)(aux + o0);
                float2 z1 = *(const float2*)(aux + o1);
                v0.x *= dsilu_f(z0.x); v0.y *= dsilu_f(z0.y);
                v1.x *= dsilu_f(z1.x); v1.y *= dsilu_f(z1.y);
            } else if (epi >= EPI_GRAD) {
                gs += v0.x * v0.x + v0.y * v0.y + v1.x * v1.x + v1.y * v1.y;
            }
            *(float2*)(C + o0) = v0;
            *(float2*)(C + o1) = v1;
        }
    }
    if (epi >= EPI_GRAD) {
        gs = block_sum(gs);
        if (t == 0) atomicAdd(gn, gs);
        if (epi == EPI_GRAD_LN && bx == 0 && by == 0) {
            float s = 0.f;
            for (int i = t; i < HH; i += NT) { float d = aux[i]; s += d * d; }
            s = block_sum(s);
            if (t == 0) atomicAdd(gn, s);
        }
    }
}

template<int BM, int BN, int WM, int WN, int NWARP, bool AT, bool BT>
__global__ __launch_bounds__(NWARP * 32) void gemm_tc(
    const float* __restrict__ A, const float* __restrict__ B,
    float* __restrict__ C, float* __restrict__ aux, float* __restrict__ gn,
    int M, int N, int K, int lda, int ldb, int epi)
{
    extern __shared__ float sm[];
    gemm_body<BM, BN, WM, WN, NWARP, AT, BT>(sm, A, B, C, aux, gn, M, N, K, lda, ldb,
                                             epi, blockIdx.x, blockIdx.y);
}

// y split-K=4
__global__ __launch_bounds__(128) void gemm_y_sk(
    const float* __restrict__ h, const float* __restrict__ w1, float* __restrict__ yp)
{
    extern __shared__ float sm[];
    int s = blockIdx.z;
    gemm_body<64, 128, 32, 64, 4, true, true>(
        sm, h + s * (II / 4), w1 + s * (II / 4), yp + (size_t)s * NN * HH,
        nullptr, nullptr, NN, HH, II / 4, II, II, EPI_NONE, blockIdx.x, blockIdx.y);
}

// fused dz / dw1
__global__ __launch_bounds__(128) void fused_dz_dw1(
    const float* __restrict__ dy, const float* __restrict__ w1,
    float* __restrict__ dz, float* __restrict__ z,
    const float* __restrict__ h, float* __restrict__ dw1, float* __restrict__ gn)
{
    extern __shared__ float sm[];
    if (blockIdx.z == 0) {
        if (blockIdx.y < 8)
            gemm_body<64, 64, 32, 32, 4, true, false>(
                sm, dy, w1, dz, z, nullptr, NN, II, HH, HH, II, EPI_DSILU,
                blockIdx.x, blockIdx.y);
    } else {
        gemm_body<64, 64, 32, 32, 4, false, false>(
            sm, dy, h, dw1, nullptr, gn, HH, II, NN, HH, II, EPI_GRAD,
            blockIdx.x, blockIdx.y);
    }
}

// ---------------- elementwise / reduction kernels ----------------
__global__ __launch_bounds__(256) void init_mem(
    const float* __restrict__ w0, const float* __restrict__ w1, const float* __restrict__ ln,
    const float* __restrict__ wk, const float* __restrict__ wv, const float* __restrict__ wq)
{
    int n = II * HH;
    for (int i = blockIdx.x * blockDim.x + threadIdx.x; i < n; i += gridDim.x * blockDim.x) {
        g_w0[i] = w0[i]; g_s0[i] = 0.f;
        g_w1[i] = w1[i]; g_s1[i] = 0.f;
        if (i < HH * HH) {
            g_wkvq16[i] = __float2half(wk[i]);
            g_wkvq16[HH * HH + i] = __float2half(wv[i]);
            g_wkvq16[2 * HH * HH + i] = __float2half(wq[i]);
        }
        if (i < HH) { g_ln[i] = ln[i]; g_sln[i] = 0.f; }
        if (i < NCH * HH) g_dlnA[i] = 0.f;
        if (i < NCH) g_gnormA[i] = 0.f;
    }
}

__global__ __launch_bounds__(256) void f2h(__half* __restrict__ dst,
                                           const float* __restrict__ src, int n4) {
    for (int i = blockIdx.x * blockDim.x + threadIdx.x; i < n4; i += gridDim.x * blockDim.x) {
        float4 v = ((const float4*)src)[i];
        ((__half2*)dst)[2 * i + 0] = __floats2half2_rn(v.x, v.y);
        ((__half2*)dst)[2 * i + 1] = __floats2half2_rn(v.z, v.w);
    }
}

// fused rmsnorm over k rows and q rows; q rows also written fp16 dense
__global__ __launch_bounds__(256) void rmsnorm_kq(const float* __restrict__ kn,
                                                  const float* __restrict__ qn) {
    int r = blockIdx.x;
    int t = threadIdx.x;
    float* rowp;
    const float* w;
    bool isq = (r >= NROWS);
    if (!isq) { rowp = g_kvq + (size_t)r * H3; w = kn; }
    else { rowp = g_kvq + (size_t)(r - NROWS) * H3 + 2 * HH; w = qn; }
    float4* row = (float4*)rowp;
    float4 v = row[t];
    float ss = v.x * v.x + v.y * v.y + v.z * v.z + v.w * v.w;
    ss = block_sum(ss);
    float rs = rsqrtf(ss / HH + 1e-6f);
    float4 wv = ((const float4*)w)[t];
    v.x *= rs * wv.x; v.y *= rs * wv.y; v.z *= rs * wv.z; v.w *= rs * wv.w;
    row[t] = v;
    if (isq) {
        __half2* q16 = (__half2*)(g_q16 + (size_t)(r - NROWS) * HH);
        q16[2 * t + 0] = __floats2half2_rn(v.x, v.y);
        q16[2 * t + 1] = __floats2half2_rn(v.z, v.w);
    }
}

__global__ __launch_bounds__(256) void gather_all() {
    const int H4 = HH / 4;
    const int W4 = H3 / 4;
    const int per = NN * H4;
    int ntot = NCH * per;
    for (int i = blockIdx.x * blockDim.x + threadIdx.x; i < ntot; i += gridDim.x * blockDim.x) {
        int c = i / per, rem = i - c * per;
        int m = rem / H4, q = rem - m * H4;
        int rr = (m >> 6) * SS + c * CC + (m & 63);
        ((float4*)g_kall)[i] = ((const float4*)g_kvq)[(size_t)rr * W4 + q];
        ((float4*)g_vall)[i] = ((const float4*)g_kvq)[(size_t)rr * W4 + H4 + q];
    }
}

__global__ __launch_bounds__(256) void coeff_dot(
    const float* __restrict__ x, const float* __restrict__ aw,
    const float* __restrict__ tw, const float* __restrict__ ew)
{
    int bc = blockIdx.x;
    int b = bc >> 5, nc = bc & 31;
    const float4* xf = (const float4*)(x + (size_t)(b * SS + nc * CC) * HH);
    const float4* a4 = (const float4*)aw;
    const float4* t4 = (const float4*)tw;
    const float4* e4 = (const float4*)ew;
    const int L4 = CC * HH / 4;
    float sa = 0.f, st = 0.f, se = 0.f;
    for (int i = threadIdx.x; i < L4; i += blockDim.x) {
        float4 xv = xf[i];
        float4 av = a4[i]; sa += xv.x * av.x + xv.y * av.y + xv.z * av.z + xv.w * av.w;
        float4 tv = t4[i]; st += xv.x * tv.x + xv.y * tv.y + xv.z * tv.z + xv.w * tv.w;
        float4 ev = e4[i]; se += xv.x * ev.x + xv.y * ev.y + xv.z * ev.z + xv.w * ev.w;
    }
    sa = block_sum(sa);
    st = block_sum(st);
    se = block_sum(se);
    if (threadIdx.x == 0) { g_dotA[bc] = sa; g_dotT[bc] = st; g_dotE[bc] = se; }
}

__global__ void coeff_finalize() {
    int t = threadIdx.x;
    if (t < BB * NCH) g_theta[t] = sigm(g_dotT[t]) * 0.01f;
    if (t < NCH) {
        float sa = 0.f, se = 0.f;
        for (int b = 0; b < BB; b++) { sa += g_dotA[b * NCH + t]; se += g_dotE[b * NCH + t]; }
        float al = sigm(sa / (float)BB);
        g_beta[t] = 1.f - al;
        g_eta[t] = sigm(se / (float)BB);
    }
}

__global__ __launch_bounds__(256) void chunk_bwd_y(int c) {
    int r = blockIdx.x;
    int t = threadIdx.x;
    int b = r >> 6;
    const float* kc = g_kall + (size_t)c * NN * HH;
    const float* vc = g_vall + (size_t)c * NN * HH;
    float4 y0 = ((const float4*)(g_y + (size_t)r * HH))[t];
    float4 y1 = ((const float4*)(g_y + (size_t)(NN + r) * HH))[t];
    float4 y2 = ((const float4*)(g_y + (size_t)(2 * NN + r) * HH))[t];
    float4 y3 = ((const float4*)(g_y + (size_t)(3 * NN + r) * HH))[t];
    float4 y4;
    y4.x = (y0.x + y1.x) + (y2.x + y3.x);
    y4.y = (y0.y + y1.y) + (y2.y + y3.y);
    y4.z = (y0.z + y1.z) + (y2.z + y3.z);
    y4.w = (y0.w + y1.w) + (y2.w + y3.w);
    float ss = y4.x * y4.x + y4.y * y4.y + y4.z * y4.z + y4.w * y4.w;
    ss = block_sum(ss);
    float rs = rsqrtf(ss / HH + 1e-6f);
    float th = g_theta[b * NCH + c];
    float scale = 2.f * th / ((float)NN * (float)HH);
    float4 k4 = ((const float4*)(kc + (size_t)r * HH))[t];
    float4 v4 = ((const float4*)(vc + (size_t)r * HH))[t];
    float4 l4 = ((const float4*)g_ln)[t];
    float4 gg;
    gg.x = scale * (k4.x + y4.x * rs * l4.x - v4.x);
    gg.y = scale * (k4.y + y4.y * rs * l4.y - v4.y);
    gg.z = scale * (k4.z + y4.z * rs * l4.z - v4.z);
    gg.w = scale * (k4.w + y4.w * rs * l4.w - v4.w);
    float sv = gg.x * l4.x * y4.x + gg.y * l4.y * y4.y + gg.z * l4.z * y4.z + gg.w * l4.w * y4.w;
    sv = block_sum(sv);
    float c3 = rs * rs * rs * sv / (float)HH;
    float4 dy;
    dy.x = rs * gg.x * l4.x - c3 * y4.x;
    dy.y = rs * gg.y * l4.y - c3 * y4.y;
    dy.z = rs * gg.z * l4.z - c3 * y4.z;
    dy.w = rs * gg.w * l4.w - c3 * y4.w;
    ((float4*)(g_dy + (size_t)r * HH))[t] = dy;
    float* dln = g_dlnA + c * HH;
    atomicAdd(&dln[t * 4 + 0], gg.x * y4.x * rs);
    atomicAdd(&dln[t * 4 + 1], gg.y * y4.y * rs);
    atomicAdd(&dln[t * 4 + 2], gg.z * y4.z * rs);
    atomicAdd(&dln[t * 4 + 3], gg.w * y4.w * rs);
}

__global__ __launch_bounds__(256) void update_params(int c) {
    float total = sqrtf(g_gnormA[c]);
    float clip = fminf(1.0f / (total + 1e-6f), 1.0f);
    float eta = g_eta[c], beta = g_beta[c];
    const float* dln = g_dlnA + c * HH;
    const int n0 = II * HH, n1 = 2 * II * HH, nt = 2 * II * HH + HH;
    for (int i = blockIdx.x * blockDim.x + threadIdx.x; i < nt; i += gridDim.x * blockDim.x) {
        if (i < n0) {
            float ns = eta * g_s0[i] - g_dw0[i] * clip;
            g_s0[i] = ns;
            g_w0[i] = beta * g_w0[i] + ns;
        } else if (i < n1) {
            int j = i - n0;
            float ns = eta * g_s1[j] - g_dw1[j] * clip;
            g_s1[j] = ns;
            g_w1[j] = beta * g_w1[j] + ns;
        } else {
            int j = i - n1;
            float ns = eta * g_sln[j] - dln[j] * clip;
            g_sln[j] = ns;
            g_ln[j] = beta * g_ln[j] + ns;
        }
    }
}

__global__ __launch_bounds__(256) void final_out(float* __restrict__ out) {
    int r = blockIdx.x, t = threadIdx.x;
    float4 y4 = ((const float4*)(g_y2 + (size_t)r * HH))[t];
    float ss = y4.x * y4.x + y4.y * y4.y + y4.z * y4.z + y4.w * y4.w;
    ss = block_sum(ss);
    float rs = rsqrtf(ss / HH + 1e-6f);
    float4 q4 = ((const float4*)(g_kvq + (size_t)r * H3 + 2 * HH))[t];
    float4 l4 = ((const float4*)g_ln)[t];
    float4 o;
    o.x = q4.x + y4.x * rs * l4.x;
    o.y = q4.y + y4.y * rs * l4.y;
    o.z = q4.z + y4.z * rs * l4.z;
    o.w = q4.w + y4.w * rs * l4.w;
    ((float4*)(out + (size_t)r * HH))[t] = o;
}

// ---------------- host launcher ----------------
extern "C" void kernel_launch(void* const* d_in, const int* in_sizes, int n_in,
                              void* d_out, int out_size) {
    const float* x   = (const float*)d_in[0];
    const float* wq  = (const float*)d_in[1];
    const float* wk  = (const float*)d_in[2];
    const float* wv  = (const float*)d_in[3];
    const float* qn  = (const float*)d_in[4];
    const float* kn  = (const float*)d_in[5];
    const float* aw  = (const float*)d_in[6];
    const float* tw  = (const float*)d_in[7];
    const float* ew  = (const float*)d_in[8];
    const float* mw0 = (const float*)d_in[9];
    const float* mw1 = (const float*)d_in[10];
    const float* mln = (const float*)d_in[11];
    float* out = (float*)d_out;

    float *kvq_, *w0_, *w1_, *kall_, *z_, *h_, *y_, *dy_, *dz_;
    float *dw0_, *dw1_, *dlnA_, *gnA_, *y2_;
    __half *x16_, *wkvq16_, *q16_, *w016_, *w116_, *h2h_;
    cudaGetSymbolAddress((void**)&kvq_,   g_kvq);
    cudaGetSymbolAddress((void**)&w0_,    g_w0);
    cudaGetSymbolAddress((void**)&w1_,    g_w1);
    cudaGetSymbolAddress((void**)&kall_,  g_kall);
    cudaGetSymbolAddress((void**)&z_,     g_z);
    cudaGetSymbolAddress((void**)&h_,     g_h);
    cudaGetSymbolAddress((void**)&y_,     g_y);
    cudaGetSymbolAddress((void**)&dy_,    g_dy);
    cudaGetSymbolAddress((void**)&dz_,    g_dz);
    cudaGetSymbolAddress((void**)&dw0_,   g_dw0);
    cudaGetSymbolAddress((void**)&dw1_,   g_dw1);
    cudaGetSymbolAddress((void**)&dlnA_,  g_dlnA);
    cudaGetSymbolAddress((void**)&gnA_,   g_gnormA);
    cudaGetSymbolAddress((void**)&y2_,    g_y2);
    cudaGetSymbolAddress((void**)&x16_,   g_x16);
    cudaGetSymbolAddress((void**)&wkvq16_,g_wkvq16);
    cudaGetSymbolAddress((void**)&q16_,   g_q16);
    cudaGetSymbolAddress((void**)&w016_,  g_w016);
    cudaGetSymbolAddress((void**)&w116_,  g_w116);
    cudaGetSymbolAddress((void**)&h2h_,   g_h2h);

    auto Gz = gemm_tc<64,64,32,32,4,true,true>;    // z = kc @ w0^T (direct)
    auto Gw = gemm_tc<64,64,32,32,4,false,false>;  // TN dw0
    const int Sz = 2 * (64*36 + 64*36) * 4;        // 36864
    const int Sy = 2 * (64*36 + 128*36) * 4;       // 55296
    const int Sw = 2 * (32*72 + 32*72) * 4;        // 36864
    const int Sf = 36864;
    const int Sh = 2 * (128*40 + 64*40) * 2;       // 30720 (fp16 gemm)
    static int attr_done = 0;
    if (!attr_done) {
        cudaFuncSetAttribute(Gz, cudaFuncAttributeMaxDynamicSharedMemorySize, Sz);
        cudaFuncSetAttribute(gemm_y_sk, cudaFuncAttributeMaxDynamicSharedMemorySize, Sy);
        cudaFuncSetAttribute(Gw, cudaFuncAttributeMaxDynamicSharedMemorySize, Sw);
        cudaFuncSetAttribute(fused_dz_dw1, cudaFuncAttributeMaxDynamicSharedMemorySize, Sf);
        cudaFuncSetAttribute(gemm_h16, cudaFuncAttributeMaxDynamicSharedMemorySize, Sh);
        attr_done = 1;
    }

    // ---- init memory params + pack fp16 kvq weights ----
    init_mem<<<2048, 256>>>(mw0, mw1, mln, wk, wv, wq);
    f2h<<<2048, 256>>>(x16_, x, NROWS * HH / 4);

    // ---- fused k|v|q projection: one fp16 GEMM, N=3072 ----
    gemm_h16<<<dim3(H3 / 64, NROWS / 128), 128, Sh>>>(
        x16_, wkvq16_, kvq_, nullptr, NROWS, H3, HH, HH, HH, HEPI_SILU_F);
    rmsnorm_kq<<<2 * NROWS, 256>>>(kn, qn);
    gather_all<<<2048, 256>>>();

    // ---- adaptive coefficients ----
    coeff_dot<<<BB * NCH, 256>>>(x, aw, tw, ew);
    coeff_finalize<<<1, 256>>>();

    // ---- sequential scan over chunks (tf32 path, unchanged) ----
    for (int c = 0; c < NCH; c++) {
        const float* kc = kall_ + (size_t)c * NN * HH;
        Gz<<<dim3(II / 64, NN / 64), 128, Sz>>>(kc, w0_, h_, z_, nullptr, NN, II, HH, HH, HH, EPI_SILU_AUX);
        gemm_y_sk<<<dim3(HH / 128, NN / 64, 4), 128, Sy>>>(h_, w1_, y_);
        chunk_bwd_y<<<NN, 256>>>(c);
        fused_dz_dw1<<<dim3(32, 16, 2), 128, Sf>>>(dy_, w1_, dz_, z_, h_, dw1_, gnA_ + c);
        Gw<<<dim3(HH / 64, II / 64), 128, Sw>>>(dz_, kc, dw0_, dlnA_ + c * HH, gnA_ + c, II, HH, NN, II, HH, EPI_GRAD_LN);
        update_params<<<1024, 256>>>(c);
    }

    // ---- retrieval with final memory (fp16 GEMMs) ----
    f2h<<<512, 256>>>(w016_, w0_, II * HH / 4);
    f2h<<<512, 256>>>(w116_, w1_, HH * II / 4);
    gemm_h16<<<dim3(II / 64, NROWS / 128), 128, Sh>>>(
        q16_, w016_, nullptr, h2h_, NROWS, II, HH, HH, HH, HEPI_SILU_H);
    gemm_h16<<<dim3(HH / 64, NROWS / 128), 128, Sh>>>(
        h2h_, w116_, y2_, nullptr, NROWS, HH, II, II, II, HEPI_NONE);
    final_out<<<NROWS, 256>>>(out);
}

// round 16
// speedup vs baseline: 1.4795x; 1.0299x over previous
#include <cuda_runtime.h>
#include <cuda_fp16.h>
#include <math.h>
#include <stdint.h>

#define BB 8
#define SS 2048
#define HH 1024
#define CC 64
#define NCH 32
#define NN 512      /* BB*CC rows per chunk */
#define II 2048     /* INTER */
#define NROWS 16384 /* BB*SS */
#define H3 3072     /* 3*HH packed kvq width */

#define EPI_NONE 0
#define EPI_SILU 1
#define EPI_SILU_AUX 2
#define EPI_DSILU 3
#define EPI_GRAD 4
#define EPI_GRAD_LN 5

// fp16 GEMM epilogues
#define HEPI_NONE 0
#define HEPI_SILU_F 1
#define HEPI_SILU_H 2
#define HEPI_SILU_AUX_FH 3

// ---------------- device scratch (no allocation allowed) ----------------
__device__ __align__(16) __half g_x16[NROWS * HH];
__device__ __align__(16) __half g_wkvq16[3 * HH * HH];
__device__ __align__(16) __half g_q16[NROWS * HH];
__device__ __align__(16) __half g_w016[II * HH];
__device__ __align__(16) __half g_w116[HH * II];
__device__ __align__(16) __half g_kall16[NROWS * HH];
__device__ __align__(16) __half g_h16[NN * II];
__device__ __align__(16) __half g_h2h[(size_t)NROWS * II];
__device__ __align__(16) float g_kvq[(size_t)NROWS * H3];
__device__ __align__(16) float g_kall[NROWS * HH];
__device__ __align__(16) float g_vall[NROWS * HH];
__device__ __align__(16) float g_w0[II * HH];
__device__ __align__(16) float g_w1[HH * II];
__device__ __align__(16) float g_ln[HH];
__device__ __align__(16) float g_s0[II * HH];
__device__ __align__(16) float g_s1[HH * II];
__device__ __align__(16) float g_sln[HH];
__device__ __align__(16) float g_z[NN * II];
__device__ __align__(16) float g_h[NN * II];
__device__ __align__(16) float g_dz[NN * II];
__device__ __align__(16) float g_y[2 * NN * HH];    /* y split-K=2 partials */
__device__ __align__(16) float g_dy[NN * HH];
__device__ __align__(16) float g_dw0[II * HH];
__device__ __align__(16) float g_dw1[HH * II];
__device__ __align__(16) float g_dlnA[NCH * HH];
__device__ __align__(16) float g_gnormA[NCH];
__device__ __align__(16) float g_y2[NROWS * HH];
__device__ __align__(16) float g_dotA[BB * NCH];
__device__ __align__(16) float g_dotT[BB * NCH];
__device__ __align__(16) float g_dotE[BB * NCH];
__device__ __align__(16) float g_beta[NCH];
__device__ __align__(16) float g_eta[NCH];
__device__ __align__(16) float g_theta[BB * NCH];

// ---------------- helpers ----------------
__device__ __forceinline__ float sigm(float x) { return 1.f / (1.f + expf(-x)); }
__device__ __forceinline__ float silu_f(float x) { return x / (1.f + expf(-x)); }
__device__ __forceinline__ float dsilu_f(float x) {
    float s = 1.f / (1.f + expf(-x));
    return s * (1.f + x * (1.f - s));
}

__device__ __forceinline__ void mma8(float* d, const uint32_t* a, const uint32_t* b) {
    asm volatile(
        "mma.sync.aligned.m16n8k8.row.col.f32.tf32.tf32.f32 "
        "{%0,%1,%2,%3}, {%4,%5,%6,%7}, {%8,%9}, {%0,%1,%2,%3};"
        : "+f"(d[0]), "+f"(d[1]), "+f"(d[2]), "+f"(d[3])
        : "r"(a[0]), "r"(a[1]), "r"(a[2]), "r"(a[3]), "r"(b[0]), "r"(b[1]));
}

__device__ __forceinline__ void mma16(float* d, const uint32_t* a, const uint32_t* b) {
    asm volatile(
        "mma.sync.aligned.m16n8k16.row.col.f32.f16.f16.f32 "
        "{%0,%1,%2,%3}, {%4,%5,%6,%7}, {%8,%9}, {%0,%1,%2,%3};"
        : "+f"(d[0]), "+f"(d[1]), "+f"(d[2]), "+f"(d[3])
        : "r"(a[0]), "r"(a[1]), "r"(a[2]), "r"(a[3]), "r"(b[0]), "r"(b[1]));
}

#define LDSM_X4(r0, r1, r2, r3, addr) \
    asm volatile("ldmatrix.sync.aligned.m8n8.x4.shared.b16 {%0,%1,%2,%3}, [%4];" \
                 : "=r"(r0), "=r"(r1), "=r"(r2), "=r"(r3) : "r"(addr))

__device__ __forceinline__ void cpa16(float* dst, const float* src) {
    uint32_t d = (uint32_t)__cvta_generic_to_shared(dst);
    asm volatile("cp.async.cg.shared.global [%0], [%1], 16;\n" :: "r"(d), "l"(src));
}
__device__ __forceinline__ void cpa16h(__half* dst, const __half* src) {
    uint32_t d = (uint32_t)__cvta_generic_to_shared(dst);
    asm volatile("cp.async.cg.shared.global [%0], [%1], 16;\n" :: "r"(d), "l"(src));
}
__device__ __forceinline__ void cpa_commit() { asm volatile("cp.async.commit_group;\n"); }

__device__ __forceinline__ float block_sum(float v) {
    __shared__ float sh[32];
    __shared__ float tot;
    int lane = threadIdx.x & 31;
    int w = threadIdx.x >> 5;
#pragma unroll
    for (int o = 16; o > 0; o >>= 1) v += __shfl_xor_sync(0xffffffffu, v, o);
    if (lane == 0) sh[w] = v;
    __syncthreads();
    if (w == 0) {
        float r = (lane < (blockDim.x >> 5)) ? sh[lane] : 0.f;
#pragma unroll
        for (int o = 16; o > 0; o >>= 1) r += __shfl_xor_sync(0xffffffffu, r, o);
        if (lane == 0) tot = r;
    }
    __syncthreads();
    return tot;
}

// ---------------- fp16 tensor-core GEMM body (NT, 4 warps, warp BM/2 x BN/2) --
// C[M,N] = A(MxK) * B(NxK)^T, fp16 inputs, fp32 accumulate.
template<int BM, int BN>
__device__ __forceinline__ void h16_body(
    __half* smh,
    const __half* __restrict__ A, const __half* __restrict__ B,
    float* __restrict__ Cf, __half* __restrict__ Ch, float* __restrict__ aux,
    int M, int N, int K, int lda, int ldb, int epi, int bx, int by)
{
    constexpr int AR = 40;                 // halfs per staged row (80B, 16B-aligned)
    constexpr int ASZ = BM * AR;
    constexpr int BSZ = BN * AR;
    constexpr int WM = BM / 2, WN = BN / 2;
    constexpr int MI = WM / 16, NI = WN / 8;
    constexpr int PA = BM * 4 / 128;
    constexpr int PB = BN * 4 / 128;
    __half* Ab[2] = { smh, smh + ASZ };
    __half* Bb[2] = { smh + 2 * ASZ, smh + 2 * ASZ + BSZ };

    const int t = threadIdx.x;
    const int bm = by * BM, bn = bx * BN;
    const int wid = t >> 5, lane = t & 31;
    const int wm = (wid & 1) * WM;
    const int wn = (wid >> 1) * WN;
    const int gp = lane >> 2, kq = lane & 3;

    const uint32_t aoh = (uint32_t)(((wm + (lane & 15)) * AR + ((lane >> 4) & 1) * 8) * 2);
    const uint32_t boh = (uint32_t)(((wn + (lane & 7) + ((lane >> 4) & 1) * 8) * AR +
                                     ((lane >> 3) & 1) * 8) * 2);
    uint32_t AsU[2] = { (uint32_t)__cvta_generic_to_shared(Ab[0]),
                        (uint32_t)__cvta_generic_to_shared(Ab[1]) };
    uint32_t BsU[2] = { (uint32_t)__cvta_generic_to_shared(Bb[0]),
                        (uint32_t)__cvta_generic_to_shared(Bb[1]) };

    float acc[MI][NI][4];
#pragma unroll
    for (int i = 0; i < MI; i++)
#pragma unroll
        for (int j = 0; j < NI; j++)
#pragma unroll
            for (int q = 0; q < 4; q++) acc[i][j][q] = 0.f;

    auto issue = [&](int k0, int buf) {
        __half* As = Ab[buf];
        __half* Bs = Bb[buf];
#pragma unroll
        for (int p = 0; p < PA; p++) {
            int idx = p * 128 + t;
            int row = idx >> 2, seg = idx & 3;
            cpa16h(As + row * AR + seg * 8, A + (size_t)(bm + row) * lda + k0 + seg * 8);
        }
#pragma unroll
        for (int p = 0; p < PB; p++) {
            int idx = p * 128 + t;
            int row = idx >> 2, seg = idx & 3;
            cpa16h(Bs + row * AR + seg * 8, B + (size_t)(bn + row) * ldb + k0 + seg * 8);
        }
        cpa_commit();
    };

    issue(0, 0);
    const int nit = K / 32;
    for (int it = 0; it < nit; it++) {
        if (it + 1 < nit) {
            issue((it + 1) * 32, (it + 1) & 1);
            asm volatile("cp.async.wait_group 1;\n");
        } else {
            asm volatile("cp.async.wait_group 0;\n");
        }
        __syncthreads();
        const int buf = it & 1;
        const uint32_t AsB = AsU[buf], BsB = BsU[buf];
#pragma unroll
        for (int ks = 0; ks < 2; ks++) {
            uint32_t af[MI][4], bf[NI][2];
#pragma unroll
            for (int mi = 0; mi < MI; mi++)
                LDSM_X4(af[mi][0], af[mi][1], af[mi][2], af[mi][3],
                        AsB + aoh + mi * (16 * AR * 2) + ks * 32);
#pragma unroll
            for (int q = 0; q < NI / 2; q++)
                LDSM_X4(bf[2 * q][0], bf[2 * q][1], bf[2 * q + 1][0], bf[2 * q + 1][1],
                        BsB + boh + q * (16 * AR * 2) + ks * 32);
#pragma unroll
            for (int mi = 0; mi < MI; mi++)
#pragma unroll
                for (int ni = 0; ni < NI; ni++)
                    mma16(acc[mi][ni], af[mi], bf[ni]);
        }
        __syncthreads();
    }

    // epilogue
#pragma unroll
    for (int mi = 0; mi < MI; mi++) {
#pragma unroll
        for (int ni = 0; ni < NI; ni++) {
            int r0 = bm + wm + mi * 16 + gp;
            int c = bn + wn + ni * 8 + kq * 2;
            size_t o0 = (size_t)r0 * N + c;
            size_t o1 = (size_t)(r0 + 8) * N + c;
            float2 v0 = make_float2(acc[mi][ni][0], acc[mi][ni][1]);
            float2 v1 = make_float2(acc[mi][ni][2], acc[mi][ni][3]);
            if (epi == HEPI_SILU_F) {
                v0.x = silu_f(v0.x); v0.y = silu_f(v0.y);
                v1.x = silu_f(v1.x); v1.y = silu_f(v1.y);
                *(float2*)(Cf + o0) = v0;
                *(float2*)(Cf + o1) = v1;
            } else if (epi == HEPI_SILU_H) {
                *(__half2*)(Ch + o0) = __floats2half2_rn(silu_f(v0.x), silu_f(v0.y));
                *(__half2*)(Ch + o1) = __floats2half2_rn(silu_f(v1.x), silu_f(v1.y));
            } else if (epi == HEPI_SILU_AUX_FH) {
                *(float2*)(aux + o0) = v0;
                *(float2*)(aux + o1) = v1;
                v0.x = silu_f(v0.x); v0.y = silu_f(v0.y);
                v1.x = silu_f(v1.x); v1.y = silu_f(v1.y);
                *(float2*)(Cf + o0) = v0;
                *(float2*)(Cf + o1) = v1;
                *(__half2*)(Ch + o0) = __floats2half2_rn(v0.x, v0.y);
                *(__half2*)(Ch + o1) = __floats2half2_rn(v1.x, v1.y);
            } else {
                *(float2*)(Cf + o0) = v0;
                *(float2*)(Cf + o1) = v1;
            }
        }
    }
}

template<int BM, int BN>
__global__ __launch_bounds__(128) void gemm_h16(
    const __half* __restrict__ A, const __half* __restrict__ B,
    float* __restrict__ Cf, __half* __restrict__ Ch, float* __restrict__ aux,
    int M, int N, int K, int lda, int ldb, int epi)
{
    extern __shared__ __half smh[];
    h16_body<BM, BN>(smh, A, B, Cf, Ch, aux, M, N, K, lda, ldb, epi,
                     blockIdx.x, blockIdx.y);
}

// y split-K=2 (fp16): yp[s][NN,HH] = h16[:, s*1024:+1024] @ w116[:, same]^T
__global__ __launch_bounds__(128) void gemm_y16_sk(
    const __half* __restrict__ h16, const __half* __restrict__ w116, float* __restrict__ yp)
{
    extern __shared__ __half smh[];
    int s = blockIdx.z;
    h16_body<64, 64>(smh, h16 + s * (II / 2), w116 + s * (II / 2),
                     yp + (size_t)s * NN * HH, nullptr, nullptr,
                     NN, HH, II / 2, II, II, HEPI_NONE, blockIdx.x, blockIdx.y);
}

// ---------------- tf32 tensor-core GEMM body (scan backward path) ------------
template<int BM, int BN, int WM, int WN, int NWARP, bool AT, bool BT>
__device__ __forceinline__ void gemm_body(
    float* sm,
    const float* __restrict__ A, const float* __restrict__ B,
    float* __restrict__ C, float* __restrict__ aux, float* __restrict__ gn,
    int M, int N, int K, int lda, int ldb, int epi, int bx, int by)
{
    constexpr int NT = NWARP * 32;
    constexpr int SA = BM + 8;
    constexpr int SB = BN + 8;
    constexpr int ASZ = AT ? BM * 36 : 32 * SA;
    constexpr int BSZ = BT ? BN * 36 : 32 * SB;
    constexpr int PA = AT ? (BM * 8) / NT : (32 * (BM / 4)) / NT;
    constexpr int PB = BT ? (BN * 8) / NT : (32 * (BN / 4)) / NT;
    constexpr int WGM = BM / WM;
    constexpr int MI = WM / 16, NI = WN / 8;

    float* Ab[2] = { sm, sm + ASZ };
    float* Bb[2] = { sm + 2 * ASZ, sm + 2 * ASZ + BSZ };

    const int t = threadIdx.x;
    const int bm = by * BM, bn = bx * BN;
    const int wid = t >> 5, lane = t & 31;
    const int wm = (wid % WGM) * WM;
    const int wn = (wid / WGM) * WN;
    const int gp = lane >> 2, kq = lane & 3;

    const int lane_row = lane & 7;
    const uint32_t ao = (uint32_t)(((wm + lane_row + ((lane >> 3) & 1) * 8) * 36 +
                                    ((lane >> 4) & 1) * 4) * 4);
    const uint32_t bo = (uint32_t)(((wn + lane_row + ((lane >> 4) & 1) * 8) * 36 +
                                    ((lane >> 3) & 1) * 4) * 4);
    uint32_t AsU[2] = { (uint32_t)__cvta_generic_to_shared(Ab[0]),
                        (uint32_t)__cvta_generic_to_shared(Ab[1]) };
    uint32_t BsU[2] = { (uint32_t)__cvta_generic_to_shared(Bb[0]),
                        (uint32_t)__cvta_generic_to_shared(Bb[1]) };

    float acc[MI][NI][4];
#pragma unroll
    for (int i = 0; i < MI; i++)
#pragma unroll
        for (int j = 0; j < NI; j++)
#pragma unroll
            for (int q = 0; q < 4; q++) acc[i][j][q] = 0.f;

    auto issue = [&](int k0, int buf) {
        float* As = Ab[buf];
        float* Bs = Bb[buf];
#pragma unroll
        for (int p = 0; p < PA; p++) {
            int idx = p * NT + t;
            if constexpr (AT) {
                int row = idx >> 3, seg = idx & 7;
                cpa16(As + row * 36 + seg * 4, A + (size_t)(bm + row) * lda + k0 + seg * 4);
            } else {
                int kk = idx / (BM / 4), mseg = idx % (BM / 4);
                cpa16(As + kk * SA + mseg * 4, A + (size_t)(k0 + kk) * lda + bm + mseg * 4);
            }
        }
#pragma unroll
        for (int p = 0; p < PB; p++) {
            int idx = p * NT + t;
            if constexpr (BT) {
                int row = idx >> 3, seg = idx & 7;
                cpa16(Bs + row * 36 + seg * 4, B + (size_t)(bn + row) * ldb + k0 + seg * 4);
            } else {
                int kk = idx / (BN / 4), nseg = idx % (BN / 4);
                cpa16(Bs + kk * SB + nseg * 4, B + (size_t)(k0 + kk) * ldb + bn + nseg * 4);
            }
        }
        cpa_commit();
    };

    issue(0, 0);
    const int nit = K / 32;
    for (int it = 0; it < nit; it++) {
        if (it + 1 < nit) {
            issue((it + 1) * 32, (it + 1) & 1);
            asm volatile("cp.async.wait_group 1;\n");
        } else {
            asm volatile("cp.async.wait_group 0;\n");
        }
        __syncthreads();
        const int buf = it & 1;
        const float* As = Ab[buf];
        const float* Bs = Bb[buf];
        const uint32_t AsB = AsU[buf], BsB = BsU[buf];
#pragma unroll
        for (int ks = 0; ks < 4; ks++) {
            const int k8 = ks * 8 + kq;
            uint32_t af[MI][4], bf[NI][2];
            if constexpr (AT) {
#pragma unroll
                for (int mi = 0; mi < MI; mi++)
                    LDSM_X4(af[mi][0], af[mi][1], af[mi][2], af[mi][3],
                            AsB + ao + mi * 2304 + ks * 32);
            } else {
#pragma unroll
                for (int mi = 0; mi < MI; mi++) {
                    int r0 = wm + mi * 16 + gp;
                    af[mi][0] = __float_as_uint(As[k8 * SA + r0]);
                    af[mi][1] = __float_as_uint(As[k8 * SA + r0 + 8]);
                    af[mi][2] = __float_as_uint(As[(k8 + 4) * SA + r0]);
                    af[mi][3] = __float_as_uint(As[(k8 + 4) * SA + r0 + 8]);
                }
            }
            if constexpr (BT) {
#pragma unroll
                for (int q = 0; q < NI / 2; q++)
                    LDSM_X4(bf[2 * q][0], bf[2 * q][1], bf[2 * q + 1][0], bf[2 * q + 1][1],
                            BsB + bo + q * 2304 + ks * 32);
            } else {
#pragma unroll
                for (int ni = 0; ni < NI; ni++) {
                    int c0 = wn + ni * 8 + gp;
                    bf[ni][0] = __float_as_uint(Bs[k8 * SB + c0]);
                    bf[ni][1] = __float_as_uint(Bs[(k8 + 4) * SB + c0]);
                }
            }
#pragma unroll
            for (int mi = 0; mi < MI; mi++)
#pragma unroll
                for (int ni = 0; ni < NI; ni++)
                    mma8(acc[mi][ni], af[mi], bf[ni]);
        }
        __syncthreads();
    }

    // epilogue
    float gs = 0.f;
#pragma unroll
    for (int mi = 0; mi < MI; mi++) {
#pragma unroll
        for (int ni = 0; ni < NI; ni++) {
            int r0 = bm + wm + mi * 16 + gp;
            int c = bn + wn + ni * 8 + kq * 2;
            size_t o0 = (size_t)r0 * N + c;
            size_t o1 = (size_t)(r0 + 8) * N + c;
            float2 v0 = make_float2(acc[mi][ni][0], acc[mi][ni][1]);
            float2 v1 = make_float2(acc[mi][ni][2], acc[mi][ni][3]);
            if (epi == EPI_DSILU) {
                float2 z0 = *(const float2*)(aux + o0);
                float2 z1 = *(const float2*)(aux + o1);
                v0.x *= dsilu_f(z0.x); v0.y *= dsilu_f(z0.y);
                v1.x *= dsilu_f(z1.x); v1.y *= dsilu_f(z1.y);
            } else if (epi >= EPI_GRAD) {
                gs += v0.x * v0.x + v0.y * v0.y + v1.x * v1.x + v1.y * v1.y;
            }
            *(float2*)(C + o0) = v0;
            *(float2*)(C + o1) = v1;
        }
    }
    if (epi >= EPI_GRAD) {
        gs = block_sum(gs);
        if (t == 0) atomicAdd(gn, gs);
        if (epi == EPI_GRAD_LN && bx == 0 && by == 0) {
            float s = 0.f;
            for (int i = t; i < HH; i += NT) { float d = aux[i]; s += d * d; }
            s = block_sum(s);
            if (t == 0) atomicAdd(gn, s);
        }
    }
}

template<int BM, int BN, int WM, int WN, int NWARP, bool AT, bool BT>
__global__ __launch_bounds__(NWARP * 32) void gemm_tc(
    const float* __restrict__ A, const float* __restrict__ B,
    float* __restrict__ C, float* __restrict__ aux, float* __restrict__ gn,
    int M, int N, int K, int lda, int ldb, int epi)
{
    extern __shared__ float sm[];
    gemm_body<BM, BN, WM, WN, NWARP, AT, BT>(sm, A, B, C, aux, gn, M, N, K, lda, ldb,
                                             epi, blockIdx.x, blockIdx.y);
}

// fused dz / dw1 (tf32 backward)
__global__ __launch_bounds__(128) void fused_dz_dw1(
    const float* __restrict__ dy, const float* __restrict__ w1,
    float* __restrict__ dz, float* __restrict__ z,
    const float* __restrict__ h, float* __restrict__ dw1, float* __restrict__ gn)
{
    extern __shared__ float sm[];
    if (blockIdx.z == 0) {
        if (blockIdx.y < 8)
            gemm_body<64, 64, 32, 32, 4, true, false>(
                sm, dy, w1, dz, z, nullptr, NN, II, HH, HH, II, EPI_DSILU,
                blockIdx.x, blockIdx.y);
    } else {
        gemm_body<64, 64, 32, 32, 4, false, false>(
            sm, dy, h, dw1, nullptr, gn, HH, II, NN, HH, II, EPI_GRAD,
            blockIdx.x, blockIdx.y);
    }
}

// ---------------- elementwise / reduction kernels ----------------
__global__ __launch_bounds__(256) void init_mem(
    const float* __restrict__ w0, const float* __restrict__ w1, const float* __restrict__ ln,
    const float* __restrict__ wk, const float* __restrict__ wv, const float* __restrict__ wq)
{
    int n = II * HH;
    for (int i = blockIdx.x * blockDim.x + threadIdx.x; i < n; i += gridDim.x * blockDim.x) {
        float a = w0[i]; g_w0[i] = a; g_w016[i] = __float2half(a); g_s0[i] = 0.f;
        float b = w1[i]; g_w1[i] = b; g_w116[i] = __float2half(b); g_s1[i] = 0.f;
        if (i < HH * HH) {
            g_wkvq16[i] = __float2half(wk[i]);
            g_wkvq16[HH * HH + i] = __float2half(wv[i]);
            g_wkvq16[2 * HH * HH + i] = __float2half(wq[i]);
        }
        if (i < HH) { g_ln[i] = ln[i]; g_sln[i] = 0.f; }
        if (i < NCH * HH) g_dlnA[i] = 0.f;
        if (i < NCH) g_gnormA[i] = 0.f;
    }
}

__global__ __launch_bounds__(256) void f2h(__half* __restrict__ dst,
                                           const float* __restrict__ src, int n4) {
    for (int i = blockIdx.x * blockDim.x + threadIdx.x; i < n4; i += gridDim.x * blockDim.x) {
        float4 v = ((const float4*)src)[i];
        ((__half2*)dst)[2 * i + 0] = __floats2half2_rn(v.x, v.y);
        ((__half2*)dst)[2 * i + 1] = __floats2half2_rn(v.z, v.w);
    }
}

// fused rmsnorm over k rows and q rows; q rows also written fp16 dense
__global__ __launch_bounds__(256) void rmsnorm_kq(const float* __restrict__ kn,
                                                  const float* __restrict__ qn) {
    int r = blockIdx.x;
    int t = threadIdx.x;
    float* rowp;
    const float* w;
    bool isq = (r >= NROWS);
    if (!isq) { rowp = g_kvq + (size_t)r * H3; w = kn; }
    else { rowp = g_kvq + (size_t)(r - NROWS) * H3 + 2 * HH; w = qn; }
    float4* row = (float4*)rowp;
    float4 v = row[t];
    float ss = v.x * v.x + v.y * v.y + v.z * v.z + v.w * v.w;
    ss = block_sum(ss);
    float rs = rsqrtf(ss / HH + 1e-6f);
    float4 wv = ((const float4*)w)[t];
    v.x *= rs * wv.x; v.y *= rs * wv.y; v.z *= rs * wv.z; v.w *= rs * wv.w;
    row[t] = v;
    if (isq) {
        __half2* q16 = (__half2*)(g_q16 + (size_t)(r - NROWS) * HH);
        q16[2 * t + 0] = __floats2half2_rn(v.x, v.y);
        q16[2 * t + 1] = __floats2half2_rn(v.z, v.w);
    }
}

__global__ __launch_bounds__(256) void gather_all() {
    const int H4 = HH / 4;
    const int W4 = H3 / 4;
    const int per = NN * H4;
    int ntot = NCH * per;
    for (int i = blockIdx.x * blockDim.x + threadIdx.x; i < ntot; i += gridDim.x * blockDim.x) {
        int c = i / per, rem = i - c * per;
        int m = rem / H4, q = rem - m * H4;
        int rr = (m >> 6) * SS + c * CC + (m & 63);
        float4 kv = ((const float4*)g_kvq)[(size_t)rr * W4 + q];
        ((float4*)g_kall)[i] = kv;
        ((__half2*)g_kall16)[2 * i + 0] = __floats2half2_rn(kv.x, kv.y);
        ((__half2*)g_kall16)[2 * i + 1] = __floats2half2_rn(kv.z, kv.w);
        ((float4*)g_vall)[i] = ((const float4*)g_kvq)[(size_t)rr * W4 + H4 + q];
    }
}

__global__ __launch_bounds__(256) void coeff_dot(
    const float* __restrict__ x, const float* __restrict__ aw,
    const float* __restrict__ tw, const float* __restrict__ ew)
{
    int bc = blockIdx.x;
    int b = bc >> 5, nc = bc & 31;
    const float4* xf = (const float4*)(x + (size_t)(b * SS + nc * CC) * HH);
    const float4* a4 = (const float4*)aw;
    const float4* t4 = (const float4*)tw;
    const float4* e4 = (const float4*)ew;
    const int L4 = CC * HH / 4;
    float sa = 0.f, st = 0.f, se = 0.f;
    for (int i = threadIdx.x; i < L4; i += blockDim.x) {
        float4 xv = xf[i];
        float4 av = a4[i]; sa += xv.x * av.x + xv.y * av.y + xv.z * av.z + xv.w * av.w;
        float4 tv = t4[i]; st += xv.x * tv.x + xv.y * tv.y + xv.z * tv.z + xv.w * tv.w;
        float4 ev = e4[i]; se += xv.x * ev.x + xv.y * ev.y + xv.z * ev.z + xv.w * ev.w;
    }
    sa = block_sum(sa);
    st = block_sum(st);
    se = block_sum(se);
    if (threadIdx.x == 0) { g_dotA[bc] = sa; g_dotT[bc] = st; g_dotE[bc] = se; }
}

__global__ void coeff_finalize() {
    int t = threadIdx.x;
    if (t < BB * NCH) g_theta[t] = sigm(g_dotT[t]) * 0.01f;
    if (t < NCH) {
        float sa = 0.f, se = 0.f;
        for (int b = 0; b < BB; b++) { sa += g_dotA[b * NCH + t]; se += g_dotE[b * NCH + t]; }
        float al = sigm(sa / (float)BB);
        g_beta[t] = 1.f - al;
        g_eta[t] = sigm(se / (float)BB);
    }
}

// backward through rmsnorm + residual + weighted MSE; combines 2 split-K y parts
__global__ __launch_bounds__(256) void chunk_bwd_y(int c) {
    int r = blockIdx.x;
    int t = threadIdx.x;
    int b = r >> 6;
    const float* kc = g_kall + (size_t)c * NN * HH;
    const float* vc = g_vall + (size_t)c * NN * HH;
    float4 ya = ((const float4*)(g_y + (size_t)r * HH))[t];
    float4 yb = ((const float4*)(g_y + (size_t)(NN + r) * HH))[t];
    float4 y4;
    y4.x = ya.x + yb.x; y4.y = ya.y + yb.y; y4.z = ya.z + yb.z; y4.w = ya.w + yb.w;
    float ss = y4.x * y4.x + y4.y * y4.y + y4.z * y4.z + y4.w * y4.w;
    ss = block_sum(ss);
    float rs = rsqrtf(ss / HH + 1e-6f);
    float th = g_theta[b * NCH + c];
    float scale = 2.f * th / ((float)NN * (float)HH);
    float4 k4 = ((const float4*)(kc + (size_t)r * HH))[t];
    float4 v4 = ((const float4*)(vc + (size_t)r * HH))[t];
    float4 l4 = ((const float4*)g_ln)[t];
    float4 gg;
    gg.x = scale * (k4.x + y4.x * rs * l4.x - v4.x);
    gg.y = scale * (k4.y + y4.y * rs * l4.y - v4.y);
    gg.z = scale * (k4.z + y4.z * rs * l4.z - v4.z);
    gg.w = scale * (k4.w + y4.w * rs * l4.w - v4.w);
    float sv = gg.x * l4.x * y4.x + gg.y * l4.y * y4.y + gg.z * l4.z * y4.z + gg.w * l4.w * y4.w;
    sv = block_sum(sv);
    float c3 = rs * rs * rs * sv / (float)HH;
    float4 dy;
    dy.x = rs * gg.x * l4.x - c3 * y4.x;
    dy.y = rs * gg.y * l4.y - c3 * y4.y;
    dy.z = rs * gg.z * l4.z - c3 * y4.z;
    dy.w = rs * gg.w * l4.w - c3 * y4.w;
    ((float4*)(g_dy + (size_t)r * HH))[t] = dy;
    float* dln = g_dlnA + c * HH;
    atomicAdd(&dln[t * 4 + 0], gg.x * y4.x * rs);
    atomicAdd(&dln[t * 4 + 1], gg.y * y4.y * rs);
    atomicAdd(&dln[t * 4 + 2], gg.z * y4.z * rs);
    atomicAdd(&dln[t * 4 + 3], gg.w * y4.w * rs);
}

__global__ __launch_bounds__(256) void update_params(int c) {
    float total = sqrtf(g_gnormA[c]);
    float clip = fminf(1.0f / (total + 1e-6f), 1.0f);
    float eta = g_eta[c], beta = g_beta[c];
    const float* dln = g_dlnA + c * HH;
    const int n0 = II * HH, n1 = 2 * II * HH, nt = 2 * II * HH + HH;
    for (int i = blockIdx.x * blockDim.x + threadIdx.x; i < nt; i += gridDim.x * blockDim.x) {
        if (i < n0) {
            float ns = eta * g_s0[i] - g_dw0[i] * clip;
            g_s0[i] = ns;
            float nw = beta * g_w0[i] + ns;
            g_w0[i] = nw;
            g_w016[i] = __float2half(nw);
        } else if (i < n1) {
            int j = i - n0;
            float ns = eta * g_s1[j] - g_dw1[j] * clip;
            g_s1[j] = ns;
            float nw = beta * g_w1[j] + ns;
            g_w1[j] = nw;
            g_w116[j] = __float2half(nw);
        } else {
            int j = i - n1;
            float ns = eta * g_sln[j] - dln[j] * clip;
            g_sln[j] = ns;
            g_ln[j] = beta * g_ln[j] + ns;
        }
    }
}

__global__ __launch_bounds__(256) void final_out(float* __restrict__ out) {
    int r = blockIdx.x, t = threadIdx.x;
    float4 y4 = ((const float4*)(g_y2 + (size_t)r * HH))[t];
    float ss = y4.x * y4.x + y4.y * y4.y + y4.z * y4.z + y4.w * y4.w;
    ss = block_sum(ss);
    float rs = rsqrtf(ss / HH + 1e-6f);
    float4 q4 = ((const float4*)(g_kvq + (size_t)r * H3 + 2 * HH))[t];
    float4 l4 = ((const float4*)g_ln)[t];
    float4 o;
    o.x = q4.x + y4.x * rs * l4.x;
    o.y = q4.y + y4.y * rs * l4.y;
    o.z = q4.z + y4.z * rs * l4.z;
    o.w = q4.w + y4.w * rs * l4.w;
    ((float4*)(out + (size_t)r * HH))[t] = o;
}

// ---------------- host launcher ----------------
extern "C" void kernel_launch(void* const* d_in, const int* in_sizes, int n_in,
                              void* d_out, int out_size) {
    const float* x   = (const float*)d_in[0];
    const float* wq  = (const float*)d_in[1];
    const float* wk  = (const float*)d_in[2];
    const float* wv  = (const float*)d_in[3];
    const float* qn  = (const float*)d_in[4];
    const float* kn  = (const float*)d_in[5];
    const float* aw  = (const float*)d_in[6];
    const float* tw  = (const float*)d_in[7];
    const float* ew  = (const float*)d_in[8];
    const float* mw0 = (const float*)d_in[9];
    const float* mw1 = (const float*)d_in[10];
    const float* mln = (const float*)d_in[11];
    float* out = (float*)d_out;

    float *kvq_, *w0_, *w1_, *kall_, *z_, *h_, *y_, *dy_, *dz_;
    float *dw0_, *dw1_, *dlnA_, *gnA_, *y2_;
    __half *x16_, *wkvq16_, *q16_, *w016_, *w116_, *kall16_, *h16_, *h2h_;
    cudaGetSymbolAddress((void**)&kvq_,    g_kvq);
    cudaGetSymbolAddress((void**)&w0_,     g_w0);
    cudaGetSymbolAddress((void**)&w1_,     g_w1);
    cudaGetSymbolAddress((void**)&kall_,   g_kall);
    cudaGetSymbolAddress((void**)&z_,      g_z);
    cudaGetSymbolAddress((void**)&h_,      g_h);
    cudaGetSymbolAddress((void**)&y_,      g_y);
    cudaGetSymbolAddress((void**)&dy_,     g_dy);
    cudaGetSymbolAddress((void**)&dz_,     g_dz);
    cudaGetSymbolAddress((void**)&dw0_,    g_dw0);
    cudaGetSymbolAddress((void**)&dw1_,    g_dw1);
    cudaGetSymbolAddress((void**)&dlnA_,   g_dlnA);
    cudaGetSymbolAddress((void**)&gnA_,    g_gnormA);
    cudaGetSymbolAddress((void**)&y2_,     g_y2);
    cudaGetSymbolAddress((void**)&x16_,    g_x16);
    cudaGetSymbolAddress((void**)&wkvq16_, g_wkvq16);
    cudaGetSymbolAddress((void**)&q16_,    g_q16);
    cudaGetSymbolAddress((void**)&w016_,   g_w016);
    cudaGetSymbolAddress((void**)&w116_,   g_w116);
    cudaGetSymbolAddress((void**)&kall16_, g_kall16);
    cudaGetSymbolAddress((void**)&h16_,    g_h16);
    cudaGetSymbolAddress((void**)&h2h_,    g_h2h);

    auto Gw = gemm_tc<64,64,32,32,4,false,false>;  // TN dw0
    auto Hbig = gemm_h16<128,64>;
    auto Hz = gemm_h16<64,64>;
    const int Sw = 2 * (32*72 + 32*72) * 4;        // 36864
    const int Sf = 36864;
    const int Sh1 = 2 * (128*40 + 64*40) * 2;      // 30720
    const int Sh2 = 2 * (64*40 + 64*40) * 2;       // 20480
    static int attr_done = 0;
    if (!attr_done) {
        cudaFuncSetAttribute(Gw, cudaFuncAttributeMaxDynamicSharedMemorySize, Sw);
        cudaFuncSetAttribute(fused_dz_dw1, cudaFuncAttributeMaxDynamicSharedMemorySize, Sf);
        cudaFuncSetAttribute(Hbig, cudaFuncAttributeMaxDynamicSharedMemorySize, Sh1);
        cudaFuncSetAttribute(Hz, cudaFuncAttributeMaxDynamicSharedMemorySize, Sh2);
        cudaFuncSetAttribute(gemm_y16_sk, cudaFuncAttributeMaxDynamicSharedMemorySize, Sh2);
        attr_done = 1;
    }

    // ---- init memory params + fp16 weight copies ----
    init_mem<<<2048, 256>>>(mw0, mw1, mln, wk, wv, wq);
    f2h<<<2048, 256>>>(x16_, x, NROWS * HH / 4);

    // ---- fused k|v|q projection: one fp16 GEMM, N=3072 ----
    Hbig<<<dim3(H3 / 64, NROWS / 128), 128, Sh1>>>(
        x16_, wkvq16_, kvq_, nullptr, nullptr, NROWS, H3, HH, HH, HH, HEPI_SILU_F);
    rmsnorm_kq<<<2 * NROWS, 256>>>(kn, qn);
    gather_all<<<2048, 256>>>();

    // ---- adaptive coefficients ----
    coeff_dot<<<BB * NCH, 256>>>(x, aw, tw, ew);
    coeff_finalize<<<1, 256>>>();

    // ---- sequential scan over chunks (fwd fp16, bwd tf32) ----
    for (int c = 0; c < NCH; c++) {
        const float* kc = kall_ + (size_t)c * NN * HH;
        const __half* kc16 = kall16_ + (size_t)c * NN * HH;
        // z = kc16 @ w016^T ; writes z fp32, h fp32, h16 — 256 blocks fp16
        Hz<<<dim3(II / 64, NN / 64), 128, Sh2>>>(
            kc16, w016_, h_, h16_, z_, NN, II, HH, HH, HH, HEPI_SILU_AUX_FH);
        // y partials (fp16 split-K=2, 256 blocks)
        gemm_y16_sk<<<dim3(HH / 64, NN / 64, 2), 128, Sh2>>>(h16_, w116_, y_);
        // backward through residual + rmsnorm + MSE (sums 2 y partials)
        chunk_bwd_y<<<NN, 256>>>(c);
        // dz || dw1 (tf32)
        fused_dz_dw1<<<dim3(32, 16, 2), 128, Sf>>>(dy_, w1_, dz_, z_, h_, dw1_, gnA_ + c);
        // dw0 = dz^T @ kc (tf32, +grad sumsq + dln^2)
        Gw<<<dim3(HH / 64, II / 64), 128, Sw>>>(dz_, kc, dw0_, dlnA_ + c * HH, gnA_ + c, II, HH, NN, II, HH, EPI_GRAD_LN);
        // clipped EMA update (+ fp16 weight copies)
        update_params<<<1024, 256>>>(c);
    }

    // ---- retrieval with final memory (fp16 GEMMs; weights16 already current) ----
    Hbig<<<dim3(II / 64, NROWS / 128), 128, Sh1>>>(
        q16_, w016_, nullptr, h2h_, nullptr, NROWS, II, HH, HH, HH, HEPI_SILU_H);
    Hbig<<<dim3(HH / 64, NROWS / 128), 128, Sh1>>>(
        h2h_, w116_, y2_, nullptr, nullptr, NROWS, HH, II, II, II, HEPI_NONE);
    final_out<<<NROWS, 256>>>(out);
}

// round 17
// speedup vs baseline: 2.0257x; 1.3692x over previous
#include <cuda_runtime.h>
#include <cuda_fp16.h>
#include <math.h>
#include <stdint.h>

#define BB 8
#define SS 2048
#define HH 1024
#define CC 64
#define NCH 32
#define NN 512      /* BB*CC rows per chunk */
#define II 2048     /* INTER */
#define NROWS 16384 /* BB*SS */
#define H3 3072     /* 3*HH packed kvq width */

#define GSCALE 16777216.0f           /* 2^24 loss scale for backward */
#define GINV   5.9604644775390625e-8f /* 2^-24 */

// fp16 GEMM epilogues
#define HEPI_NONE 0
#define HEPI_SILU_F 1
#define HEPI_SILU_H 2
#define HEPI_SILU_AUX_H 3
#define HEPI_DSILU_H 4
#define HEPI_GRAD16 5
#define HEPI_GRAD16_LN 6

// ---------------- device scratch (no allocation allowed) ----------------
__device__ __align__(16) __half g_x16[NROWS * HH];
__device__ __align__(16) __half g_wkvq16[3 * HH * HH];
__device__ __align__(16) __half g_q16[NROWS * HH];
__device__ __align__(16) __half g_w016[II * HH];
__device__ __align__(16) __half g_w116[HH * II];
__device__ __align__(16) __half g_kall16[NROWS * HH];
__device__ __align__(16) __half g_h16[NN * II];
__device__ __align__(16) __half g_dy16[NN * HH];
__device__ __align__(16) __half g_dz16[NN * II];
__device__ __align__(16) __half g_h2h[(size_t)NROWS * II];
__device__ __align__(16) float g_kvq[(size_t)NROWS * H3];
__device__ __align__(16) float g_kall[NROWS * HH];
__device__ __align__(16) float g_vall[NROWS * HH];
__device__ __align__(16) float g_w0[II * HH];
__device__ __align__(16) float g_w1[HH * II];
__device__ __align__(16) float g_ln[HH];
__device__ __align__(16) float g_s0[II * HH];
__device__ __align__(16) float g_s1[HH * II];
__device__ __align__(16) float g_sln[HH];
__device__ __align__(16) float g_z[NN * II];
__device__ __align__(16) float g_y[2 * NN * HH];    /* y split-K=2 partials */
__device__ __align__(16) float g_dw0[II * HH];
__device__ __align__(16) float g_dw1[HH * II];
__device__ __align__(16) float g_dlnA[NCH * HH];
__device__ __align__(16) float g_gnormA[NCH];
__device__ __align__(16) float g_y2[NROWS * HH];
__device__ __align__(16) float g_dotA[BB * NCH];
__device__ __align__(16) float g_dotT[BB * NCH];
__device__ __align__(16) float g_dotE[BB * NCH];
__device__ __align__(16) float g_beta[NCH];
__device__ __align__(16) float g_eta[NCH];
__device__ __align__(16) float g_theta[BB * NCH];

// ---------------- helpers ----------------
__device__ __forceinline__ float sigm(float x) { return 1.f / (1.f + expf(-x)); }
__device__ __forceinline__ float silu_f(float x) { return x / (1.f + expf(-x)); }
__device__ __forceinline__ float dsilu_f(float x) {
    float s = 1.f / (1.f + expf(-x));
    return s * (1.f + x * (1.f - s));
}

__device__ __forceinline__ void mma16(float* d, const uint32_t* a, const uint32_t* b) {
    asm volatile(
        "mma.sync.aligned.m16n8k16.row.col.f32.f16.f16.f32 "
        "{%0,%1,%2,%3}, {%4,%5,%6,%7}, {%8,%9}, {%0,%1,%2,%3};"
        : "+f"(d[0]), "+f"(d[1]), "+f"(d[2]), "+f"(d[3])
        : "r"(a[0]), "r"(a[1]), "r"(a[2]), "r"(a[3]), "r"(b[0]), "r"(b[1]));
}

#define LDSM_X4(r0, r1, r2, r3, addr) \
    asm volatile("ldmatrix.sync.aligned.m8n8.x4.shared.b16 {%0,%1,%2,%3}, [%4];" \
                 : "=r"(r0), "=r"(r1), "=r"(r2), "=r"(r3) : "r"(addr))
#define LDSM_X4T(r0, r1, r2, r3, addr) \
    asm volatile("ldmatrix.sync.aligned.m8n8.x4.trans.shared.b16 {%0,%1,%2,%3}, [%4];" \
                 : "=r"(r0), "=r"(r1), "=r"(r2), "=r"(r3) : "r"(addr))

__device__ __forceinline__ void cpa16h(__half* dst, const __half* src) {
    uint32_t d = (uint32_t)__cvta_generic_to_shared(dst);
    asm volatile("cp.async.cg.shared.global [%0], [%1], 16;\n" :: "r"(d), "l"(src));
}
__device__ __forceinline__ void cpa_commit() { asm volatile("cp.async.commit_group;\n"); }

__device__ __forceinline__ float block_sum(float v) {
    __shared__ float sh[32];
    __shared__ float tot;
    int lane = threadIdx.x & 31;
    int w = threadIdx.x >> 5;
#pragma unroll
    for (int o = 16; o > 0; o >>= 1) v += __shfl_xor_sync(0xffffffffu, v, o);
    if (lane == 0) sh[w] = v;
    __syncthreads();
    if (w == 0) {
        float r = (lane < (blockDim.x >> 5)) ? sh[lane] : 0.f;
#pragma unroll
        for (int o = 16; o > 0; o >>= 1) r += __shfl_xor_sync(0xffffffffu, r, o);
        if (lane == 0) tot = r;
    }
    __syncthreads();
    return tot;
}

// ---------------- fp16 tensor-core GEMM body (4 warps, warp BM/2 x BN/2) -----
// AT=true : A is M x K row-major  (ldmatrix normal)
// AT=false: A is K x M row-major  (=A^T, ldmatrix.trans)
// BT=true : B is N x K row-major  (ldmatrix normal)
// BT=false: B is K x N row-major  (ldmatrix.trans)
template<int BM, int BN, bool AT, bool BT>
__device__ __forceinline__ void h16_body(
    __half* smh,
    const __half* __restrict__ A, const __half* __restrict__ B,
    float* __restrict__ Cf, __half* __restrict__ Ch, float* __restrict__ aux,
    float* __restrict__ gn,
    int M, int N, int K, int lda, int ldb, int epi, int bx, int by)
{
    constexpr int ARr = 40;
    constexpr int ARk = BM + 8;
    constexpr int BRr = 40;
    constexpr int BRk = BN + 8;
    constexpr int ASZ = AT ? BM * ARr : 32 * ARk;
    constexpr int BSZ = BT ? BN * BRr : 32 * BRk;
    constexpr int WM = BM / 2, WN = BN / 2;
    constexpr int MI = WM / 16, NI = WN / 8;
    constexpr int PA = BM * 4 / 128;
    constexpr int PB = BN * 4 / 128;
    __half* Ab[2] = { smh, smh + ASZ };
    __half* Bb[2] = { smh + 2 * ASZ, smh + 2 * ASZ + BSZ };

    const int t = threadIdx.x;
    const int bm = by * BM, bn = bx * BN;
    const int wid = t >> 5, lane = t & 31;
    const int wm = (wid & 1) * WM;
    const int wn = (wid >> 1) * WN;
    const int gp = lane >> 2, kq = lane & 3;

    const uint32_t ao = AT
        ? (uint32_t)(((wm + (lane & 15)) * ARr + ((lane >> 4) & 1) * 8) * 2)
        : (uint32_t)((((lane & 7) + ((lane >> 4) & 1) * 8) * ARk + wm + ((lane >> 3) & 1) * 8) * 2);
    const uint32_t bo = BT
        ? (uint32_t)(((wn + (lane & 7) + ((lane >> 4) & 1) * 8) * BRr + ((lane >> 3) & 1) * 8) * 2)
        : (uint32_t)((((lane & 7) + ((lane >> 3) & 1) * 8) * BRk + wn + ((lane >> 4) & 1) * 8) * 2);
    uint32_t AsU[2] = { (uint32_t)__cvta_generic_to_shared(Ab[0]),
                        (uint32_t)__cvta_generic_to_shared(Ab[1]) };
    uint32_t BsU[2] = { (uint32_t)__cvta_generic_to_shared(Bb[0]),
                        (uint32_t)__cvta_generic_to_shared(Bb[1]) };

    float acc[MI][NI][4];
#pragma unroll
    for (int i = 0; i < MI; i++)
#pragma unroll
        for (int j = 0; j < NI; j++)
#pragma unroll
            for (int q = 0; q < 4; q++) acc[i][j][q] = 0.f;

    auto issue = [&](int k0, int buf) {
        __half* As = Ab[buf];
        __half* Bs = Bb[buf];
#pragma unroll
        for (int p = 0; p < PA; p++) {
            int idx = p * 128 + t;
            if constexpr (AT) {
                int row = idx >> 2, seg = idx & 3;
                cpa16h(As + row * ARr + seg * 8, A + (size_t)(bm + row) * lda + k0 + seg * 8);
            } else {
                int kk = idx / (BM / 8), seg = idx % (BM / 8);
                cpa16h(As + kk * ARk + seg * 8, A + (size_t)(k0 + kk) * lda + bm + seg * 8);
            }
        }
#pragma unroll
        for (int p = 0; p < PB; p++) {
            int idx = p * 128 + t;
            if constexpr (BT) {
                int row = idx >> 2, seg = idx & 3;
                cpa16h(Bs + row * BRr + seg * 8, B + (size_t)(bn + row) * ldb + k0 + seg * 8);
            } else {
                int kk = idx / (BN / 8), seg = idx % (BN / 8);
                cpa16h(Bs + kk * BRk + seg * 8, B + (size_t)(k0 + kk) * ldb + bn + seg * 8);
            }
        }
        cpa_commit();
    };

    issue(0, 0);
    const int nit = K / 32;
    for (int it = 0; it < nit; it++) {
        if (it + 1 < nit) {
            issue((it + 1) * 32, (it + 1) & 1);
            asm volatile("cp.async.wait_group 1;\n");
        } else {
            asm volatile("cp.async.wait_group 0;\n");
        }
        __syncthreads();
        const int buf = it & 1;
        const uint32_t AsB = AsU[buf], BsB = BsU[buf];
#pragma unroll
        for (int ks = 0; ks < 2; ks++) {
            uint32_t af[MI][4], bf[NI][2];
#pragma unroll
            for (int mi = 0; mi < MI; mi++) {
                if constexpr (AT)
                    LDSM_X4(af[mi][0], af[mi][1], af[mi][2], af[mi][3],
                            AsB + ao + mi * (16 * ARr * 2) + ks * 32);
                else
                    LDSM_X4T(af[mi][0], af[mi][1], af[mi][2], af[mi][3],
                             AsB + ao + ks * (16 * ARk * 2) + mi * 32);
            }
#pragma unroll
            for (int q = 0; q < NI / 2; q++) {
                if constexpr (BT)
                    LDSM_X4(bf[2 * q][0], bf[2 * q][1], bf[2 * q + 1][0], bf[2 * q + 1][1],
                            BsB + bo + q * (16 * BRr * 2) + ks * 32);
                else
                    LDSM_X4T(bf[2 * q][0], bf[2 * q][1], bf[2 * q + 1][0], bf[2 * q + 1][1],
                             BsB + bo + ks * (16 * BRk * 2) + q * 32);
            }
#pragma unroll
            for (int mi = 0; mi < MI; mi++)
#pragma unroll
                for (int ni = 0; ni < NI; ni++)
                    mma16(acc[mi][ni], af[mi], bf[ni]);
        }
        __syncthreads();
    }

    // epilogue
    float gs = 0.f;
#pragma unroll
    for (int mi = 0; mi < MI; mi++) {
#pragma unroll
        for (int ni = 0; ni < NI; ni++) {
            int r0 = bm + wm + mi * 16 + gp;
            int c = bn + wn + ni * 8 + kq * 2;
            size_t o0 = (size_t)r0 * N + c;
            size_t o1 = (size_t)(r0 + 8) * N + c;
            float2 v0 = make_float2(acc[mi][ni][0], acc[mi][ni][1]);
            float2 v1 = make_float2(acc[mi][ni][2], acc[mi][ni][3]);
            if (epi == HEPI_SILU_F) {
                *(float2*)(Cf + o0) = make_float2(silu_f(v0.x), silu_f(v0.y));
                *(float2*)(Cf + o1) = make_float2(silu_f(v1.x), silu_f(v1.y));
            } else if (epi == HEPI_SILU_H) {
                *(__half2*)(Ch + o0) = __floats2half2_rn(silu_f(v0.x), silu_f(v0.y));
                *(__half2*)(Ch + o1) = __floats2half2_rn(silu_f(v1.x), silu_f(v1.y));
            } else if (epi == HEPI_SILU_AUX_H) {
                *(float2*)(aux + o0) = v0;
                *(float2*)(aux + o1) = v1;
                *(__half2*)(Ch + o0) = __floats2half2_rn(silu_f(v0.x), silu_f(v0.y));
                *(__half2*)(Ch + o1) = __floats2half2_rn(silu_f(v1.x), silu_f(v1.y));
            } else if (epi == HEPI_DSILU_H) {
                float2 z0 = *(const float2*)(aux + o0);
                float2 z1 = *(const float2*)(aux + o1);
                *(__half2*)(Ch + o0) = __floats2half2_rn(v0.x * dsilu_f(z0.x), v0.y * dsilu_f(z0.y));
                *(__half2*)(Ch + o1) = __floats2half2_rn(v1.x * dsilu_f(z1.x), v1.y * dsilu_f(z1.y));
            } else if (epi >= HEPI_GRAD16) {
                v0.x *= GINV; v0.y *= GINV; v1.x *= GINV; v1.y *= GINV;
                gs += v0.x * v0.x + v0.y * v0.y + v1.x * v1.x + v1.y * v1.y;
                *(float2*)(Cf + o0) = v0;
                *(float2*)(Cf + o1) = v1;
            } else {
                *(float2*)(Cf + o0) = v0;
                *(float2*)(Cf + o1) = v1;
            }
        }
    }
    if (epi >= HEPI_GRAD16) {
        gs = block_sum(gs);
        if (t == 0) atomicAdd(gn, gs);
        if (epi == HEPI_GRAD16_LN && bx == 0 && by == 0) {
            float s = 0.f;
            for (int i = t; i < HH; i += 128) { float d = aux[i]; s += d * d; }
            s = block_sum(s);
            if (t == 0) atomicAdd(gn, s);
        }
    }
}

template<int BM, int BN, bool AT, bool BT>
__global__ __launch_bounds__(128) void gemm_h16(
    const __half* __restrict__ A, const __half* __restrict__ B,
    float* __restrict__ Cf, __half* __restrict__ Ch, float* __restrict__ aux,
    float* __restrict__ gn,
    int M, int N, int K, int lda, int ldb, int epi)
{
    extern __shared__ __half smh[];
    h16_body<BM, BN, AT, BT>(smh, A, B, Cf, Ch, aux, gn, M, N, K, lda, ldb, epi,
                             blockIdx.x, blockIdx.y);
}

// y split-K=2 (fp16)
__global__ __launch_bounds__(128) void gemm_y16_sk(
    const __half* __restrict__ h16, const __half* __restrict__ w116, float* __restrict__ yp)
{
    extern __shared__ __half smh[];
    int s = blockIdx.z;
    h16_body<64, 64, true, true>(smh, h16 + s * (II / 2), w116 + s * (II / 2),
                                 yp + (size_t)s * NN * HH, nullptr, nullptr, nullptr,
                                 NN, HH, II / 2, II, II, HEPI_NONE, blockIdx.x, blockIdx.y);
}

// fused: z==0 (by<8): dz16 = (dy16 @ w1) * dsilu(z)   grid (32,8)
//        z==1       : dw1 = dy16^T @ h16 (unscaled) + grad  grid (32,16)
__global__ __launch_bounds__(128) void fused_dz_dw1(float* __restrict__ gn) {
    extern __shared__ __half smh[];
    if (blockIdx.z == 0) {
        if (blockIdx.y < 8)
            h16_body<64, 64, true, false>(smh, g_dy16, g_w116, nullptr, g_dz16, g_z, nullptr,
                                          NN, II, HH, HH, II, HEPI_DSILU_H,
                                          blockIdx.x, blockIdx.y);
    } else {
        h16_body<64, 64, false, false>(smh, g_dy16, g_h16, g_dw1, nullptr, nullptr, gn,
                                       HH, II, NN, HH, II, HEPI_GRAD16,
                                       blockIdx.x, blockIdx.y);
    }
}

// dw0 = dz16^T @ kall16 (unscaled) + grad + dln^2
__global__ __launch_bounds__(128) void gemm_dw0(const __half* __restrict__ kc16,
                                                float* __restrict__ dln, float* __restrict__ gn) {
    extern __shared__ __half smh[];
    h16_body<64, 64, false, false>(smh, g_dz16, kc16, g_dw0, nullptr, dln, gn,
                                   II, HH, NN, II, HH, HEPI_GRAD16_LN,
                                   blockIdx.x, blockIdx.y);
}

// ---------------- elementwise / reduction kernels ----------------
__global__ __launch_bounds__(256) void init_mem(
    const float* __restrict__ w0, const float* __restrict__ w1, const float* __restrict__ ln,
    const float* __restrict__ wk, const float* __restrict__ wv, const float* __restrict__ wq)
{
    int n = II * HH;
    for (int i = blockIdx.x * blockDim.x + threadIdx.x; i < n; i += gridDim.x * blockDim.x) {
        float a = w0[i]; g_w0[i] = a; g_w016[i] = __float2half(a); g_s0[i] = 0.f;
        float b = w1[i]; g_w1[i] = b; g_w116[i] = __float2half(b); g_s1[i] = 0.f;
        if (i < HH * HH) {
            g_wkvq16[i] = __float2half(wk[i]);
            g_wkvq16[HH * HH + i] = __float2half(wv[i]);
            g_wkvq16[2 * HH * HH + i] = __float2half(wq[i]);
        }
        if (i < HH) { g_ln[i] = ln[i]; g_sln[i] = 0.f; }
        if (i < NCH * HH) g_dlnA[i] = 0.f;
        if (i < NCH) g_gnormA[i] = 0.f;
    }
}

__global__ __launch_bounds__(256) void f2h(__half* __restrict__ dst,
                                           const float* __restrict__ src, int n4) {
    for (int i = blockIdx.x * blockDim.x + threadIdx.x; i < n4; i += gridDim.x * blockDim.x) {
        float4 v = ((const float4*)src)[i];
        ((__half2*)dst)[2 * i + 0] = __floats2half2_rn(v.x, v.y);
        ((__half2*)dst)[2 * i + 1] = __floats2half2_rn(v.z, v.w);
    }
}

// fused rmsnorm over k rows and q rows; q rows also written fp16 dense
__global__ __launch_bounds__(256) void rmsnorm_kq(const float* __restrict__ kn,
                                                  const float* __restrict__ qn) {
    int r = blockIdx.x;
    int t = threadIdx.x;
    float* rowp;
    const float* w;
    bool isq = (r >= NROWS);
    if (!isq) { rowp = g_kvq + (size_t)r * H3; w = kn; }
    else { rowp = g_kvq + (size_t)(r - NROWS) * H3 + 2 * HH; w = qn; }
    float4* row = (float4*)rowp;
    float4 v = row[t];
    float ss = v.x * v.x + v.y * v.y + v.z * v.z + v.w * v.w;
    ss = block_sum(ss);
    float rs = rsqrtf(ss / HH + 1e-6f);
    float4 wv = ((const float4*)w)[t];
    v.x *= rs * wv.x; v.y *= rs * wv.y; v.z *= rs * wv.z; v.w *= rs * wv.w;
    row[t] = v;
    if (isq) {
        __half2* q16 = (__half2*)(g_q16 + (size_t)(r - NROWS) * HH);
        q16[2 * t + 0] = __floats2half2_rn(v.x, v.y);
        q16[2 * t + 1] = __floats2half2_rn(v.z, v.w);
    }
}

__global__ __launch_bounds__(256) void gather_all() {
    const int H4 = HH / 4;
    const int W4 = H3 / 4;
    const int per = NN * H4;
    int ntot = NCH * per;
    for (int i = blockIdx.x * blockDim.x + threadIdx.x; i < ntot; i += gridDim.x * blockDim.x) {
        int c = i / per, rem = i - c * per;
        int m = rem / H4, q = rem - m * H4;
        int rr = (m >> 6) * SS + c * CC + (m & 63);
        float4 kv = ((const float4*)g_kvq)[(size_t)rr * W4 + q];
        ((float4*)g_kall)[i] = kv;
        ((__half2*)g_kall16)[2 * i + 0] = __floats2half2_rn(kv.x, kv.y);
        ((__half2*)g_kall16)[2 * i + 1] = __floats2half2_rn(kv.z, kv.w);
        ((float4*)g_vall)[i] = ((const float4*)g_kvq)[(size_t)rr * W4 + H4 + q];
    }
}

__global__ __launch_bounds__(256) void coeff_dot(
    const float* __restrict__ x, const float* __restrict__ aw,
    const float* __restrict__ tw, const float* __restrict__ ew)
{
    int bc = blockIdx.x;
    int b = bc >> 5, nc = bc & 31;
    const float4* xf = (const float4*)(x + (size_t)(b * SS + nc * CC) * HH);
    const float4* a4 = (const float4*)aw;
    const float4* t4 = (const float4*)tw;
    const float4* e4 = (const float4*)ew;
    const int L4 = CC * HH / 4;
    float sa = 0.f, st = 0.f, se = 0.f;
    for (int i = threadIdx.x; i < L4; i += blockDim.x) {
        float4 xv = xf[i];
        float4 av = a4[i]; sa += xv.x * av.x + xv.y * av.y + xv.z * av.z + xv.w * av.w;
        float4 tv = t4[i]; st += xv.x * tv.x + xv.y * tv.y + xv.z * tv.z + xv.w * tv.w;
        float4 ev = e4[i]; se += xv.x * ev.x + xv.y * ev.y + xv.z * ev.z + xv.w * ev.w;
    }
    sa = block_sum(sa);
    st = block_sum(st);
    se = block_sum(se);
    if (threadIdx.x == 0) { g_dotA[bc] = sa; g_dotT[bc] = st; g_dotE[bc] = se; }
}

__global__ void coeff_finalize() {
    int t = threadIdx.x;
    if (t < BB * NCH) g_theta[t] = sigm(g_dotT[t]) * 0.01f;
    if (t < NCH) {
        float sa = 0.f, se = 0.f;
        for (int b = 0; b < BB; b++) { sa += g_dotA[b * NCH + t]; se += g_dotE[b * NCH + t]; }
        float al = sigm(sa / (float)BB);
        g_beta[t] = 1.f - al;
        g_eta[t] = sigm(se / (float)BB);
    }
}

// backward through rmsnorm + residual + weighted MSE; dy written fp16 * 2^24
__global__ __launch_bounds__(256) void chunk_bwd_y(int c) {
    int r = blockIdx.x;
    int t = threadIdx.x;
    int b = r >> 6;
    const float* kc = g_kall + (size_t)c * NN * HH;
    const float* vc = g_vall + (size_t)c * NN * HH;
    float4 ya = ((const float4*)(g_y + (size_t)r * HH))[t];
    float4 yb = ((const float4*)(g_y + (size_t)(NN + r) * HH))[t];
    float4 y4;
    y4.x = ya.x + yb.x; y4.y = ya.y + yb.y; y4.z = ya.z + yb.z; y4.w = ya.w + yb.w;
    float ss = y4.x * y4.x + y4.y * y4.y + y4.z * y4.z + y4.w * y4.w;
    ss = block_sum(ss);
    float rs = rsqrtf(ss / HH + 1e-6f);
    float th = g_theta[b * NCH + c];
    float scale = 2.f * th / ((float)NN * (float)HH);
    float4 k4 = ((const float4*)(kc + (size_t)r * HH))[t];
    float4 v4 = ((const float4*)(vc + (size_t)r * HH))[t];
    float4 l4 = ((const float4*)g_ln)[t];
    float4 gg;
    gg.x = scale * (k4.x + y4.x * rs * l4.x - v4.x);
    gg.y = scale * (k4.y + y4.y * rs * l4.y - v4.y);
    gg.z = scale * (k4.z + y4.z * rs * l4.z - v4.z);
    gg.w = scale * (k4.w + y4.w * rs * l4.w - v4.w);
    float sv = gg.x * l4.x * y4.x + gg.y * l4.y * y4.y + gg.z * l4.z * y4.z + gg.w * l4.w * y4.w;
    sv = block_sum(sv);
    float c3 = rs * rs * rs * sv / (float)HH;
    float4 dy;
    dy.x = rs * gg.x * l4.x - c3 * y4.x;
    dy.y = rs * gg.y * l4.y - c3 * y4.y;
    dy.z = rs * gg.z * l4.z - c3 * y4.z;
    dy.w = rs * gg.w * l4.w - c3 * y4.w;
    __half2* dy16 = (__half2*)(g_dy16 + (size_t)r * HH);
    dy16[2 * t + 0] = __floats2half2_rn(dy.x * GSCALE, dy.y * GSCALE);
    dy16[2 * t + 1] = __floats2half2_rn(dy.z * GSCALE, dy.w * GSCALE);
    float* dln = g_dlnA + c * HH;
    atomicAdd(&dln[t * 4 + 0], gg.x * y4.x * rs);
    atomicAdd(&dln[t * 4 + 1], gg.y * y4.y * rs);
    atomicAdd(&dln[t * 4 + 2], gg.z * y4.z * rs);
    atomicAdd(&dln[t * 4 + 3], gg.w * y4.w * rs);
}

__global__ __launch_bounds__(256) void update_params(int c) {
    float total = sqrtf(g_gnormA[c]);
    float clip = fminf(1.0f / (total + 1e-6f), 1.0f);
    float eta = g_eta[c], beta = g_beta[c];
    const float* dln = g_dlnA + c * HH;
    const int n4 = II * HH / 4;
    int tid = blockIdx.x * blockDim.x + threadIdx.x;
    int stride = gridDim.x * blockDim.x;
    for (int i = tid; i < 2 * n4; i += stride) {
        float4 *sp, *wp;
        const float4* gp4;
        __half2* hp;
        int j;
        if (i < n4) { j = i; sp = (float4*)g_s0; wp = (float4*)g_w0; gp4 = (const float4*)g_dw0; hp = (__half2*)g_w016; }
        else { j = i - n4; sp = (float4*)g_s1; wp = (float4*)g_w1; gp4 = (const float4*)g_dw1; hp = (__half2*)g_w116; }
        float4 s = sp[j], g = gp4[j], w = wp[j];
        s.x = eta * s.x - g.x * clip; s.y = eta * s.y - g.y * clip;
        s.z = eta * s.z - g.z * clip; s.w = eta * s.w - g.w * clip;
        w.x = beta * w.x + s.x; w.y = beta * w.y + s.y;
        w.z = beta * w.z + s.z; w.w = beta * w.w + s.w;
        sp[j] = s; wp[j] = w;
        hp[2 * j + 0] = __floats2half2_rn(w.x, w.y);
        hp[2 * j + 1] = __floats2half2_rn(w.z, w.w);
    }
    if (tid < HH) {
        float ns = eta * g_sln[tid] - dln[tid] * clip;
        g_sln[tid] = ns;
        g_ln[tid] = beta * g_ln[tid] + ns;
    }
}

__global__ __launch_bounds__(256) void final_out(float* __restrict__ out) {
    int r = blockIdx.x, t = threadIdx.x;
    float4 y4 = ((const float4*)(g_y2 + (size_t)r * HH))[t];
    float ss = y4.x * y4.x + y4.y * y4.y + y4.z * y4.z + y4.w * y4.w;
    ss = block_sum(ss);
    float rs = rsqrtf(ss / HH + 1e-6f);
    float4 q4 = ((const float4*)(g_kvq + (size_t)r * H3 + 2 * HH))[t];
    float4 l4 = ((const float4*)g_ln)[t];
    float4 o;
    o.x = q4.x + y4.x * rs * l4.x;
    o.y = q4.y + y4.y * rs * l4.y;
    o.z = q4.z + y4.z * rs * l4.z;
    o.w = q4.w + y4.w * rs * l4.w;
    ((float4*)(out + (size_t)r * HH))[t] = o;
}

// ---------------- host launcher ----------------
extern "C" void kernel_launch(void* const* d_in, const int* in_sizes, int n_in,
                              void* d_out, int out_size) {
    const float* x   = (const float*)d_in[0];
    const float* wq  = (const float*)d_in[1];
    const float* wk  = (const float*)d_in[2];
    const float* wv  = (const float*)d_in[3];
    const float* qn  = (const float*)d_in[4];
    const float* kn  = (const float*)d_in[5];
    const float* aw  = (const float*)d_in[6];
    const float* tw  = (const float*)d_in[7];
    const float* ew  = (const float*)d_in[8];
    const float* mw0 = (const float*)d_in[9];
    const float* mw1 = (const float*)d_in[10];
    const float* mln = (const float*)d_in[11];
    float* out = (float*)d_out;

    float *kvq_, *z_, *y_, *dlnA_, *gnA_, *y2_;
    __half *x16_, *wkvq16_, *q16_, *w016_, *w116_, *kall16_, *h16_, *h2h_;
    cudaGetSymbolAddress((void**)&kvq_,    g_kvq);
    cudaGetSymbolAddress((void**)&z_,      g_z);
    cudaGetSymbolAddress((void**)&y_,      g_y);
    cudaGetSymbolAddress((void**)&dlnA_,   g_dlnA);
    cudaGetSymbolAddress((void**)&gnA_,    g_gnormA);
    cudaGetSymbolAddress((void**)&y2_,     g_y2);
    cudaGetSymbolAddress((void**)&x16_,    g_x16);
    cudaGetSymbolAddress((void**)&wkvq16_, g_wkvq16);
    cudaGetSymbolAddress((void**)&q16_,    g_q16);
    cudaGetSymbolAddress((void**)&w016_,   g_w016);
    cudaGetSymbolAddress((void**)&w116_,   g_w116);
    cudaGetSymbolAddress((void**)&kall16_, g_kall16);
    cudaGetSymbolAddress((void**)&h16_,    g_h16);
    cudaGetSymbolAddress((void**)&h2h_,    g_h2h);

    auto Hbig = gemm_h16<128, 64, true, true>;
    auto Hz   = gemm_h16<64, 64, true, true>;
    const int Sh1 = 2 * (128 * 40 + 64 * 40) * 2;  // 30720
    const int Sh2 = 2 * (64 * 40 + 64 * 40) * 2;   // 20480
    const int Sfz = 2 * (64 * 40 + 32 * 72) * 2;   // 19456 (dz: AT normal, BT trans)
    const int Sww = 2 * (32 * 72 + 32 * 72) * 2;   // 18432 (double trans)
    const int Sf  = Sfz > Sww ? Sfz : Sww;
    static int attr_done = 0;
    if (!attr_done) {
        cudaFuncSetAttribute(Hbig, cudaFuncAttributeMaxDynamicSharedMemorySize, Sh1);
        cudaFuncSetAttribute(Hz, cudaFuncAttributeMaxDynamicSharedMemorySize, Sh2);
        cudaFuncSetAttribute(gemm_y16_sk, cudaFuncAttributeMaxDynamicSharedMemorySize, Sh2);
        cudaFuncSetAttribute(fused_dz_dw1, cudaFuncAttributeMaxDynamicSharedMemorySize, Sf);
        cudaFuncSetAttribute(gemm_dw0, cudaFuncAttributeMaxDynamicSharedMemorySize, Sww);
        attr_done = 1;
    }

    // ---- init memory params + fp16 weight copies ----
    init_mem<<<2048, 256>>>(mw0, mw1, mln, wk, wv, wq);
    f2h<<<2048, 256>>>(x16_, x, NROWS * HH / 4);

    // ---- fused k|v|q projection: one fp16 GEMM, N=3072 ----
    Hbig<<<dim3(H3 / 64, NROWS / 128), 128, Sh1>>>(
        x16_, wkvq16_, kvq_, nullptr, nullptr, nullptr, NROWS, H3, HH, HH, HH, HEPI_SILU_F);
    rmsnorm_kq<<<2 * NROWS, 256>>>(kn, qn);
    gather_all<<<2048, 256>>>();

    // ---- adaptive coefficients ----
    coeff_dot<<<BB * NCH, 256>>>(x, aw, tw, ew);
    coeff_finalize<<<1, 256>>>();

    // ---- sequential scan over chunks (all fp16; backward loss-scaled 2^24) ----
    for (int c = 0; c < NCH; c++) {
        const __half* kc16 = kall16_ + (size_t)c * NN * HH;
        // z (fp32 aux) + h16 = silu(z)
        Hz<<<dim3(II / 64, NN / 64), 128, Sh2>>>(
            kc16, w016_, nullptr, h16_, z_, nullptr, NN, II, HH, HH, HH, HEPI_SILU_AUX_H);
        // y partials (split-K=2)
        gemm_y16_sk<<<dim3(HH / 64, NN / 64, 2), 128, Sh2>>>(h16_, w116_, y_);
        // backward rmsnorm+MSE → dy16 (scaled 2^24), dln atomics
        chunk_bwd_y<<<NN, 256>>>(c);
        // dz16 (scaled) || dw1 (unscaled fp32 + grad sumsq)
        fused_dz_dw1<<<dim3(32, 16, 2), 128, Sf>>>(gnA_ + c);
        // dw0 (unscaled fp32 + grad sumsq + dln^2)
        gemm_dw0<<<dim3(HH / 64, II / 64), 128, Sww>>>(kc16, dlnA_ + c * HH, gnA_ + c);
        // clipped EMA update (vectorized, + fp16 weight copies)
        update_params<<<1024, 256>>>(c);
    }

    // ---- retrieval with final memory (fp16 GEMMs) ----
    Hbig<<<dim3(II / 64, NROWS / 128), 128, Sh1>>>(
        q16_, w016_, nullptr, h2h_, nullptr, nullptr, NROWS, II, HH, HH, HH, HEPI_SILU_H);
    Hbig<<<dim3(HH / 64, NROWS / 128), 128, Sh1>>>(
        h2h_, w116_, y2_, nullptr, nullptr, nullptr, NROWS, HH, II, II, II, HEPI_NONE);
    final_out<<<NROWS, 256>>>(out);
}